// round 2
// baseline (speedup 1.0000x reference)
#include <cuda_runtime.h>
#include <math.h>

#define BV 2
#define TV 2048
#define CV 1024
#define HV 16
#define DHV 64
#define MV (BV * TV)   // 4096

// Scratch (allocation-free rule: __device__ globals)
__device__ float g_q[(size_t)MV * CV];
__device__ float g_k[(size_t)MV * CV];
__device__ float g_v[(size_t)MV * CV];
__device__ float g_y[(size_t)MV * CV];

__device__ __forceinline__ float fast_exp2(float x) {
    float r;
    asm("ex2.approx.f32 %0, %1;" : "=f"(r) : "f"(x));
    return r;
}

// ---------------------------------------------------------------------------
// C[M,N] = A[M,K] @ W[N,K]^T   (both K-contiguous; einsum 'btc,oc->bto')
// 128x128x16 tile, 256 threads, 8x8 micro-tile, register prefetch.
// blockIdx.z selects among 3 (W, C) pairs so QKV is one launch (768 blocks).
// ---------------------------------------------------------------------------
__global__ __launch_bounds__(256, 2)
void sgemm3(const float* __restrict__ A,
            const float* __restrict__ W0,
            const float* __restrict__ W1,
            const float* __restrict__ W2,
            float* __restrict__ C0,
            float* __restrict__ C1,
            float* __restrict__ C2)
{
    constexpr int BM = 128, BN = 128, BK = 16, K = CV, N = CV;
    __shared__ float As[BK][BM + 4];
    __shared__ float Bs[BK][BN + 4];

    const float* W = (blockIdx.z == 0) ? W0 : ((blockIdx.z == 1) ? W1 : W2);
    float*      Cm = (blockIdx.z == 0) ? C0 : ((blockIdx.z == 1) ? C1 : C2);

    const int tid = threadIdx.x;
    const int bm = blockIdx.y * BM;
    const int bn = blockIdx.x * BN;

    const int lrow = tid >> 2;          // 0..63
    const int lcol = (tid & 3) << 2;    // 0,4,8,12

    const float* Ap = A + (size_t)(bm + lrow) * K + lcol;
    const float* Wp = W + (size_t)(bn + lrow) * K + lcol;

    // prefetch tile kt=0
    float4 pa0 = *(const float4*)(Ap);
    float4 pa1 = *(const float4*)(Ap + 64 * K);
    float4 pb0 = *(const float4*)(Wp);
    float4 pb1 = *(const float4*)(Wp + 64 * K);

    const int ty = tid >> 4;
    const int tx = tid & 15;
    const int m0 = ty * 8;
    const int n0 = tx * 8;

    float acc[8][8];
#pragma unroll
    for (int i = 0; i < 8; ++i)
#pragma unroll
        for (int j = 0; j < 8; ++j) acc[i][j] = 0.f;

    const int NT = K / BK;
    for (int kt = 0; kt < NT; ++kt) {
        As[lcol + 0][lrow]      = pa0.x;
        As[lcol + 1][lrow]      = pa0.y;
        As[lcol + 2][lrow]      = pa0.z;
        As[lcol + 3][lrow]      = pa0.w;
        As[lcol + 0][lrow + 64] = pa1.x;
        As[lcol + 1][lrow + 64] = pa1.y;
        As[lcol + 2][lrow + 64] = pa1.z;
        As[lcol + 3][lrow + 64] = pa1.w;
        Bs[lcol + 0][lrow]      = pb0.x;
        Bs[lcol + 1][lrow]      = pb0.y;
        Bs[lcol + 2][lrow]      = pb0.z;
        Bs[lcol + 3][lrow]      = pb0.w;
        Bs[lcol + 0][lrow + 64] = pb1.x;
        Bs[lcol + 1][lrow + 64] = pb1.y;
        Bs[lcol + 2][lrow + 64] = pb1.z;
        Bs[lcol + 3][lrow + 64] = pb1.w;
        __syncthreads();

        if (kt + 1 < NT) {   // prefetch next tile under the FFMA loop
            const float* Ap2 = Ap + (kt + 1) * BK;
            const float* Wp2 = Wp + (kt + 1) * BK;
            pa0 = *(const float4*)(Ap2);
            pa1 = *(const float4*)(Ap2 + 64 * K);
            pb0 = *(const float4*)(Wp2);
            pb1 = *(const float4*)(Wp2 + 64 * K);
        }

#pragma unroll
        for (int k = 0; k < BK; ++k) {
            float4 a0 = *(const float4*)(&As[k][m0]);
            float4 a1 = *(const float4*)(&As[k][m0 + 4]);
            float4 b0 = *(const float4*)(&Bs[k][n0]);
            float4 b1 = *(const float4*)(&Bs[k][n0 + 4]);
            float av[8] = {a0.x, a0.y, a0.z, a0.w, a1.x, a1.y, a1.z, a1.w};
            float bv[8] = {b0.x, b0.y, b0.z, b0.w, b1.x, b1.y, b1.z, b1.w};
#pragma unroll
            for (int i = 0; i < 8; ++i)
#pragma unroll
                for (int j = 0; j < 8; ++j)
                    acc[i][j] = fmaf(av[i], bv[j], acc[i][j]);
        }
        __syncthreads();
    }

#pragma unroll
    for (int i = 0; i < 8; ++i) {
        float* cp = Cm + (size_t)(bm + m0 + i) * N + bn + n0;
        *(float4*)(cp)     = make_float4(acc[i][0], acc[i][1], acc[i][2], acc[i][3]);
        *(float4*)(cp + 4) = make_float4(acc[i][4], acc[i][5], acc[i][6], acc[i][7]);
    }
}

// ---------------------------------------------------------------------------
// RoPE on q and k, in place. One thread per (b,t,h,j<32) rotates pair (j, j+32).
// ---------------------------------------------------------------------------
__global__ void rope_kernel()
{
    const int idx = blockIdx.x * blockDim.x + threadIdx.x;   // exactly B*T*H*32
    const int j = idx & 31;
    const int h = (idx >> 5) & (HV - 1);
    const int t = (idx >> 9) & (TV - 1);
    const int b = idx >> 20;

    const float L2_10000 = 13.287712379549449f;
    const float invf = exp2f(-(float)j * (L2_10000 / 32.0f));  // 10000^{-j/32}
    const float ang = (float)t * invf;
    float sn, cs;
    sincosf(ang, &sn, &cs);

    const size_t base = (size_t)(b * TV + t) * CV + h * DHV + j;
    float q1 = g_q[base], q2 = g_q[base + 32];
    g_q[base]      = q1 * cs - q2 * sn;
    g_q[base + 32] = q2 * cs + q1 * sn;
    float k1 = g_k[base], k2 = g_k[base + 32];
    g_k[base]      = k1 * cs - k2 * sn;
    g_k[base + 32] = k2 * cs + k1 * sn;
}

// ---------------------------------------------------------------------------
// Retention attention + fused GroupNorm epilogue.
// Block = (qt, b*H+h): 64 query rows x DH=64. 128 threads, 8(i) x 4(j/d) tiles.
// Causal key-tile loop. S-tile reuses the k smem buffer (transposed) between
// the two GEMMs. Decay applied via ex2.approx(dist * log2(gamma)).
// Row stride 68 floats (272 B, 16B multiple) keeps every float4 smem access
// aligned (stride 65 trapped with "misaligned address" on LDS.128).
// Dynamic smem: qs[64][68] + ks[64][68] + vs[64][64] = 51200 B.
// ---------------------------------------------------------------------------
#define ATTN_STRIDE 68
#define SMEM_ATTN ((2 * 64 * ATTN_STRIDE + 64 * 64) * sizeof(float))

__global__ __launch_bounds__(128)
void retention_attn(const float* __restrict__ gn_w, const float* __restrict__ gn_b)
{
    extern __shared__ float smem[];
    float (*qs)[ATTN_STRIDE] = (float(*)[ATTN_STRIDE])(smem);                     // qs[d][i]
    float (*ks)[ATTN_STRIDE] = (float(*)[ATTN_STRIDE])(smem + 64 * ATTN_STRIDE);  // ks[d][j], reused as S^T[j][i]
    float (*vs)[64] = (float(*)[64])(smem + 2 * 64 * ATTN_STRIDE);                // vs[j][d]

    const int qt = (int)(gridDim.x - 1 - blockIdx.x);  // biggest blocks first
    const int bh = blockIdx.y;
    const int b = bh >> 4;
    const int h = bh & 15;

    const int tid = threadIdx.x;
    const int tx = tid & 15;       // 0..15 -> 4-wide col group
    const int ti = tid >> 4;       // 0..7  -> 8-wide row group
    const int i0 = ti * 8;
    const int c0 = tx * 4;

    const float gamma = 1.0f - __int_as_float((127 - 5 - h) << 23);  // exact 1 - 2^-(5+h)
    const float l2g = log2f(gamma);

    const int tq0 = qt * 64;
    const int lr = tid >> 4;
    const int lc = (tid & 15) * 4;

    const float* qbase = g_q + (size_t)(b * TV + tq0) * CV + h * DHV;
#pragma unroll
    for (int l = 0; l < 8; ++l) {
        float4 qv = *(const float4*)(qbase + (size_t)(lr + l * 8) * CV + lc);
        qs[lc + 0][lr + l * 8] = qv.x;
        qs[lc + 1][lr + l * 8] = qv.y;
        qs[lc + 2][lr + l * 8] = qv.z;
        qs[lc + 3][lr + l * 8] = qv.w;
    }

    float o[8][4];
#pragma unroll
    for (int i = 0; i < 8; ++i)
#pragma unroll
        for (int d = 0; d < 4; ++d) o[i][d] = 0.f;

    const float scale = 0.125f;  // 1/sqrt(64)

    for (int kt = 0; kt <= qt; ++kt) {
        const int tk0 = kt * 64;
        const float* kb = g_k + (size_t)(b * TV + tk0) * CV + h * DHV;
        const float* vb = g_v + (size_t)(b * TV + tk0) * CV + h * DHV;

        __syncthreads();  // previous O-gemm done with ks/vs (also covers qs on iter 0)
#pragma unroll
        for (int l = 0; l < 8; ++l) {
            float4 kv = *(const float4*)(kb + (size_t)(lr + l * 8) * CV + lc);
            ks[lc + 0][lr + l * 8] = kv.x;
            ks[lc + 1][lr + l * 8] = kv.y;
            ks[lc + 2][lr + l * 8] = kv.z;
            ks[lc + 3][lr + l * 8] = kv.w;
            float4 vv = *(const float4*)(vb + (size_t)(lr + l * 8) * CV + lc);
            *(float4*)(&vs[lr + l * 8][lc]) = vv;
        }
        __syncthreads();

        // S = q @ k^T (8x4 per thread)
        float s[8][4];
#pragma unroll
        for (int i = 0; i < 8; ++i)
#pragma unroll
            for (int j = 0; j < 4; ++j) s[i][j] = 0.f;

#pragma unroll 16
        for (int d = 0; d < 64; ++d) {
            float4 a0 = *(const float4*)(&qs[d][i0]);
            float4 a1 = *(const float4*)(&qs[d][i0 + 4]);
            float4 bk = *(const float4*)(&ks[d][c0]);
            float av[8] = {a0.x, a0.y, a0.z, a0.w, a1.x, a1.y, a1.z, a1.w};
            float bw[4] = {bk.x, bk.y, bk.z, bk.w};
#pragma unroll
            for (int i = 0; i < 8; ++i)
#pragma unroll
                for (int j = 0; j < 4; ++j)
                    s[i][j] = fmaf(av[i], bw[j], s[i][j]);
        }

        // decay * scale (mask only needed on the diagonal tile)
        if (kt == qt) {
#pragma unroll
            for (int ii = 0; ii < 8; ++ii)
#pragma unroll
                for (int jj = 0; jj < 4; ++jj) {
                    int dist = (i0 + ii) - (c0 + jj);
                    s[ii][jj] = (dist >= 0)
                        ? s[ii][jj] * scale * fast_exp2((float)dist * l2g)
                        : 0.f;
                }
        } else {
            const int dbase = tq0 - tk0;
#pragma unroll
            for (int ii = 0; ii < 8; ++ii)
#pragma unroll
                for (int jj = 0; jj < 4; ++jj) {
                    float dist = (float)(dbase + (i0 + ii) - (c0 + jj));
                    s[ii][jj] *= scale * fast_exp2(dist * l2g);
                }
        }

        __syncthreads();  // everyone done reading ks before it becomes S^T
#pragma unroll
        for (int jj = 0; jj < 4; ++jj) {
            *(float4*)(&ks[c0 + jj][i0])     = make_float4(s[0][jj], s[1][jj], s[2][jj], s[3][jj]);
            *(float4*)(&ks[c0 + jj][i0 + 4]) = make_float4(s[4][jj], s[5][jj], s[6][jj], s[7][jj]);
        }
        __syncthreads();

        // O += S @ v
#pragma unroll 16
        for (int j = 0; j < 64; ++j) {
            float4 a0 = *(const float4*)(&ks[j][i0]);
            float4 a1 = *(const float4*)(&ks[j][i0 + 4]);
            float4 bv4 = *(const float4*)(&vs[j][c0]);
            float av[8] = {a0.x, a0.y, a0.z, a0.w, a1.x, a1.y, a1.z, a1.w};
            float bw[4] = {bv4.x, bv4.y, bv4.z, bv4.w};
#pragma unroll
            for (int ii = 0; ii < 8; ++ii)
#pragma unroll
                for (int dd = 0; dd < 4; ++dd)
                    o[ii][dd] = fmaf(av[ii], bw[dd], o[ii][dd]);
        }
    }

    // Fused GroupNorm over DH=64 per row (width-16 shfl reductions) + store (b,t,c)
    float4 gwv = *(const float4*)(gn_w + h * DHV + c0);
    float4 gbv = *(const float4*)(gn_b + h * DHV + c0);
    float wv[4] = {gwv.x, gwv.y, gwv.z, gwv.w};
    float bb[4] = {gbv.x, gbv.y, gbv.z, gbv.w};
    const float invn = 1.0f / 64.0f;

#pragma unroll
    for (int ii = 0; ii < 8; ++ii) {
        float sum = 0.f, sq = 0.f;
#pragma unroll
        for (int dd = 0; dd < 4; ++dd) { sum += o[ii][dd]; sq += o[ii][dd] * o[ii][dd]; }
#pragma unroll
        for (int off = 1; off < 16; off <<= 1) {
            sum += __shfl_xor_sync(0xffffffffu, sum, off);
            sq  += __shfl_xor_sync(0xffffffffu, sq,  off);
        }
        float mean = sum * invn;
        float var = sq * invn - mean * mean;
        float rs = rsqrtf(var + 1e-5f);
        float4 ov;
        ov.x = (o[ii][0] - mean) * rs * wv[0] + bb[0];
        ov.y = (o[ii][1] - mean) * rs * wv[1] + bb[1];
        ov.z = (o[ii][2] - mean) * rs * wv[2] + bb[2];
        ov.w = (o[ii][3] - mean) * rs * wv[3] + bb[3];
        *(float4*)(g_y + (size_t)(b * TV + tq0 + i0 + ii) * CV + h * DHV + c0) = ov;
    }
}

// ---------------------------------------------------------------------------
extern "C" void kernel_launch(void* const* d_in, const int* in_sizes, int n_in,
                              void* d_out, int out_size)
{
    const float* x   = (const float*)d_in[0];
    const float* Wq  = (const float*)d_in[1];
    const float* Wk  = (const float*)d_in[2];
    const float* Wv  = (const float*)d_in[3];
    const float* Wo  = (const float*)d_in[4];
    const float* gnw = (const float*)d_in[5];
    const float* gnb = (const float*)d_in[6];
    float* out = (float*)d_out;

    float *q, *k, *v, *y;
    cudaGetSymbolAddress((void**)&q, g_q);
    cudaGetSymbolAddress((void**)&k, g_k);
    cudaGetSymbolAddress((void**)&v, g_v);
    cudaGetSymbolAddress((void**)&y, g_y);

    cudaFuncSetAttribute(retention_attn,
                         cudaFuncAttributeMaxDynamicSharedMemorySize,
                         (int)SMEM_ATTN);

    // 1) QKV projections (one launch, z selects weight/output)
    sgemm3<<<dim3(CV / 128, MV / 128, 3), 256>>>(x, Wq, Wk, Wv, q, k, v);
    // 2) RoPE on q,k
    rope_kernel<<<(BV * TV * HV * 32) / 256, 256>>>();
    // 3) Retention + fused GroupNorm -> g_y in (b,t,c) layout
    retention_attn<<<dim3(TV / 64, BV * HV), 128, SMEM_ATTN>>>(gnw, gnb);
    // 4) Output projection
    sgemm3<<<dim3(CV / 128, MV / 128, 1), 256>>>(y, Wo, Wo, Wo, out, out, out);
}

// round 5
// speedup vs baseline: 1.5937x; 1.5937x over previous
#include <cuda_runtime.h>
#include <cuda_bf16.h>
#include <math.h>
#include <stdint.h>

#define BV 2
#define TV 2048
#define CV 1024
#define HV 16
#define DHV 64
#define MV (BV * TV)   // 4096

// ---------------------------------------------------------------------------
// Scratch (__device__ globals; allocation-free rule)
// ---------------------------------------------------------------------------
__device__ float g_q[(size_t)MV * CV];
__device__ float g_k[(size_t)MV * CV];
__device__ float g_v[(size_t)MV * CV];
__device__ float g_y[(size_t)MV * CV];

__device__ __nv_bfloat16 g_xh[(size_t)MV * CV];       // x (then y) hi
__device__ __nv_bfloat16 g_xl[(size_t)MV * CV];       // x (then y) lo
__device__ __nv_bfloat16 g_wh[(size_t)3 * CV * CV];   // Wq,Wk,Wv hi
__device__ __nv_bfloat16 g_wl[(size_t)3 * CV * CV];   // Wq,Wk,Wv lo
__device__ __nv_bfloat16 g_woh[(size_t)CV * CV];      // Wo hi
__device__ __nv_bfloat16 g_wol[(size_t)CV * CV];      // Wo lo

// ---------------------------------------------------------------------------
// helpers
// ---------------------------------------------------------------------------
__device__ __forceinline__ uint32_t smem_to_u32(const void* p) {
    uint32_t a;
    asm("{ .reg .u64 t; cvta.to.shared.u64 t, %1; cvt.u32.u64 %0, t; }"
        : "=r"(a) : "l"(p));
    return a;
}

__device__ __forceinline__ void cp16(uint32_t saddr, const void* g) {
    asm volatile("cp.async.cg.shared.global [%0], [%1], 16;"
                 :: "r"(saddr), "l"(g) : "memory");
}
__device__ __forceinline__ void cp_commit() {
    asm volatile("cp.async.commit_group;" ::: "memory");
}
__device__ __forceinline__ void cp_wait1() {
    asm volatile("cp.async.wait_group 1;" ::: "memory");
}
__device__ __forceinline__ void cp_wait0() {
    asm volatile("cp.async.wait_group 0;" ::: "memory");
}

__device__ __forceinline__ void ldsm4(uint32_t& r0, uint32_t& r1,
                                      uint32_t& r2, uint32_t& r3, uint32_t addr) {
    asm volatile("ldmatrix.sync.aligned.m8n8.x4.shared.b16 {%0,%1,%2,%3}, [%4];"
                 : "=r"(r0), "=r"(r1), "=r"(r2), "=r"(r3) : "r"(addr));
}

__device__ __forceinline__ void mma_bf16(float* c, const uint32_t* a, const uint32_t* b) {
    asm volatile(
        "mma.sync.aligned.m16n8k16.row.col.f32.bf16.bf16.f32 "
        "{%0,%1,%2,%3}, {%4,%5,%6,%7}, {%8,%9}, {%0,%1,%2,%3};"
        : "+f"(c[0]), "+f"(c[1]), "+f"(c[2]), "+f"(c[3])
        : "r"(a[0]), "r"(a[1]), "r"(a[2]), "r"(a[3]), "r"(b[0]), "r"(b[1]));
}

__device__ __forceinline__ float fast_exp2(float x) {
    float r;
    asm("ex2.approx.f32 %0, %1;" : "=f"(r) : "f"(x));
    return r;
}

// ---------------------------------------------------------------------------
// fp32 -> (bf16 hi, bf16 lo) split. 4 elements per thread.
// ---------------------------------------------------------------------------
__global__ void conv_hilo(const float* __restrict__ src,
                          __nv_bfloat16* __restrict__ hi,
                          __nv_bfloat16* __restrict__ lo, int n4)
{
    int i = blockIdx.x * blockDim.x + threadIdx.x;
    if (i >= n4) return;
    float4 v = ((const float4*)src)[i];
    __nv_bfloat16 h0 = __float2bfloat16(v.x);
    __nv_bfloat16 h1 = __float2bfloat16(v.y);
    __nv_bfloat16 h2 = __float2bfloat16(v.z);
    __nv_bfloat16 h3 = __float2bfloat16(v.w);
    __nv_bfloat16 l0 = __float2bfloat16(v.x - __bfloat162float(h0));
    __nv_bfloat16 l1 = __float2bfloat16(v.y - __bfloat162float(h1));
    __nv_bfloat16 l2 = __float2bfloat16(v.z - __bfloat162float(h2));
    __nv_bfloat16 l3 = __float2bfloat16(v.w - __bfloat162float(h3));
    ushort4 hv, lv;
    hv.x = __bfloat16_as_ushort(h0); hv.y = __bfloat16_as_ushort(h1);
    hv.z = __bfloat16_as_ushort(h2); hv.w = __bfloat16_as_ushort(h3);
    lv.x = __bfloat16_as_ushort(l0); lv.y = __bfloat16_as_ushort(l1);
    lv.z = __bfloat16_as_ushort(l2); lv.w = __bfloat16_as_ushort(l3);
    ((ushort4*)hi)[i] = hv;
    ((ushort4*)lo)[i] = lv;
}

// ---------------------------------------------------------------------------
// Warp-MMA bf16 GEMM with hi/lo fp32 emulation (mma.sync m16n8k16, HMMA).
// C[M,N] = A[M,K] @ W[N,K]^T via Ah*Wh + Ah*Wl + Al*Wh, fp32 accumulators.
// CTA 128x128, K-chunk 64, 8 warps (4m x 2n), warp tile 32x64.
// SMEM: 2 stages x { Ah, Al, Wh, Wl } tiles of 128 rows x 128 B (SW128 XOR).
// cp.async double-buffered pipeline. grid.z selects among 3 (W, C) pairs.
// ---------------------------------------------------------------------------
#define STAGE_BYTES 65536
#define OFF_AH 0
#define OFF_AL 16384
#define OFF_BH 32768
#define OFF_BL 49152
#define GEMM_SMEM (2 * STAGE_BYTES)

__global__ __launch_bounds__(256)
void bfgemm(const __nv_bfloat16* __restrict__ Ah,
            const __nv_bfloat16* __restrict__ Al,
            const __nv_bfloat16* __restrict__ Wh0,
            const __nv_bfloat16* __restrict__ Wl0,
            float* __restrict__ C0, float* __restrict__ C1, float* __restrict__ C2)
{
    extern __shared__ char smem[];
    const uint32_t sb = smem_to_u32(smem);
    const int tid = threadIdx.x;
    const int wid = tid >> 5;
    const int lane = tid & 31;
    const int z = blockIdx.z;

    const __nv_bfloat16* Wh = Wh0 + (size_t)z * CV * CV;
    const __nv_bfloat16* Wl = Wl0 + (size_t)z * CV * CV;
    float* C = (z == 0) ? C0 : ((z == 1) ? C1 : C2);

    const int bm = blockIdx.y * 128;
    const int bn = blockIdx.x * 128;
    const int warp_m = wid >> 1;       // 0..3 -> 32-row slab
    const int warp_n = wid & 1;        // 0..1 -> 64-col slab

    // loader: 1024 16B-chunks per tile, 4 per thread per matrix
    const int l_row = tid >> 1;                   // unused helper removed
    (void)l_row;

    float c[2][8][4];
#pragma unroll
    for (int mb = 0; mb < 2; ++mb)
#pragma unroll
        for (int nb = 0; nb < 8; ++nb)
#pragma unroll
            for (int e = 0; e < 4; ++e) c[mb][nb][e] = 0.f;

    // ---- issue loads of chunk ch into stage ----
    auto issue = [&](int ch, int stage) {
        const int kc0 = ch * 64;                 // element k offset
        const uint32_t base = sb + stage * STAGE_BYTES;
#pragma unroll
        for (int it = 0; it < 4; ++it) {
            const int idx = it * 256 + tid;      // 0..1023
            const int row = idx >> 3;            // 0..127
            const int colb = (idx & 7) * 16;     // byte col within 128B row
            const uint32_t sw = (uint32_t)(row * 128 + (colb ^ ((row & 7) << 4)));
            const size_t gA = (size_t)(bm + row) * CV + kc0 + (colb >> 1);
            const size_t gB = (size_t)(bn + row) * CV + kc0 + (colb >> 1);
            cp16(base + OFF_AH + sw, Ah + gA);
            cp16(base + OFF_AL + sw, Al + gA);
            cp16(base + OFF_BH + sw, Wh + gB);
            cp16(base + OFF_BL + sw, Wl + gB);
        }
        cp_commit();
    };

    issue(0, 0);

    // per-lane ldmatrix row/col selectors
    const int a_row16 = lane & 15;                 // row within 16
    const int a_koffb = ((lane >> 4) & 1) * 16;    // 0 or 16 bytes (k half)
    const int b_rowsel = (lane & 7) + ((lane >> 4) & 1) * 8;  // row within 16
    const int b_koffb = ((lane >> 3) & 1) * 16;

    const int NT = 16;
    for (int ch = 0; ch < NT; ++ch) {
        if (ch + 1 < NT) issue(ch + 1, (ch + 1) & 1);
        if (ch + 1 < NT) cp_wait1(); else cp_wait0();
        __syncthreads();

        const uint32_t base = sb + (ch & 1) * STAGE_BYTES;
#pragma unroll
        for (int ks = 0; ks < 4; ++ks) {
            const int kb = ks * 32;                // bytes into the 128B row

            uint32_t ah[2][4], al[2][4];
#pragma unroll
            for (int mb = 0; mb < 2; ++mb) {
                const int r = warp_m * 32 + mb * 16 + a_row16;
                const uint32_t ad = base + (uint32_t)(r * 128 +
                                     ((kb + a_koffb) ^ ((r & 7) << 4)));
                ldsm4(ah[mb][0], ah[mb][1], ah[mb][2], ah[mb][3], ad + OFF_AH);
                ldsm4(al[mb][0], al[mb][1], al[mb][2], al[mb][3], ad + OFF_AL);
            }

            uint32_t bh[8][2], bl[8][2];
#pragma unroll
            for (int nq = 0; nq < 4; ++nq) {
                const int r = warp_n * 64 + nq * 16 + b_rowsel;
                const uint32_t bd = base + (uint32_t)(r * 128 +
                                     ((kb + b_koffb) ^ ((r & 7) << 4)));
                uint32_t t0, t1, t2, t3;
                ldsm4(t0, t1, t2, t3, bd + OFF_BH);
                bh[nq * 2][0] = t0; bh[nq * 2][1] = t1;
                bh[nq * 2 + 1][0] = t2; bh[nq * 2 + 1][1] = t3;
                ldsm4(t0, t1, t2, t3, bd + OFF_BL);
                bl[nq * 2][0] = t0; bl[nq * 2][1] = t1;
                bl[nq * 2 + 1][0] = t2; bl[nq * 2 + 1][1] = t3;
            }

#pragma unroll
            for (int mb = 0; mb < 2; ++mb)
#pragma unroll
                for (int nb = 0; nb < 8; ++nb) {
                    mma_bf16(c[mb][nb], ah[mb], bh[nb]);
                    mma_bf16(c[mb][nb], ah[mb], bl[nb]);
                    mma_bf16(c[mb][nb], al[mb], bh[nb]);
                }
        }
        __syncthreads();
    }

    // epilogue: fragment -> global (float2 stores)
    const int gr = lane >> 2;
    const int gc = (lane & 3) * 2;
#pragma unroll
    for (int mb = 0; mb < 2; ++mb) {
        const int row0 = bm + warp_m * 32 + mb * 16 + gr;
#pragma unroll
        for (int nb = 0; nb < 8; ++nb) {
            const int col = bn + warp_n * 64 + nb * 8 + gc;
            *(float2*)(C + (size_t)row0 * CV + col) =
                make_float2(c[mb][nb][0], c[mb][nb][1]);
            *(float2*)(C + (size_t)(row0 + 8) * CV + col) =
                make_float2(c[mb][nb][2], c[mb][nb][3]);
        }
    }
}

// ---------------------------------------------------------------------------
// RoPE on q and k, in place. One thread per (b,t,h,j<32) rotates pair (j, j+32).
// ---------------------------------------------------------------------------
__global__ void rope_kernel()
{
    const int idx = blockIdx.x * blockDim.x + threadIdx.x;   // exactly B*T*H*32
    const int j = idx & 31;
    const int h = (idx >> 5) & (HV - 1);
    const int t = (idx >> 9) & (TV - 1);
    const int b = idx >> 20;

    const float L2_10000 = 13.287712379549449f;
    const float invf = exp2f(-(float)j * (L2_10000 / 32.0f));  // 10000^{-j/32}
    const float ang = (float)t * invf;
    float sn, cs;
    sincosf(ang, &sn, &cs);

    const size_t base = (size_t)(b * TV + t) * CV + h * DHV + j;
    float q1 = g_q[base], q2 = g_q[base + 32];
    g_q[base]      = q1 * cs - q2 * sn;
    g_q[base + 32] = q2 * cs + q1 * sn;
    float k1 = g_k[base], k2 = g_k[base + 32];
    g_k[base]      = k1 * cs - k2 * sn;
    g_k[base + 32] = k2 * cs + k1 * sn;
}

// ---------------------------------------------------------------------------
// Retention attention + fused GroupNorm epilogue (unchanged from R2 PASS).
// ---------------------------------------------------------------------------
#define ATTN_STRIDE 68
#define SMEM_ATTN ((2 * 64 * ATTN_STRIDE + 64 * 64) * sizeof(float))

__global__ __launch_bounds__(128)
void retention_attn(const float* __restrict__ gn_w, const float* __restrict__ gn_b)
{
    extern __shared__ float smemf[];
    float (*qs)[ATTN_STRIDE] = (float(*)[ATTN_STRIDE])(smemf);
    float (*ks)[ATTN_STRIDE] = (float(*)[ATTN_STRIDE])(smemf + 64 * ATTN_STRIDE);
    float (*vs)[64] = (float(*)[64])(smemf + 2 * 64 * ATTN_STRIDE);

    const int qt = (int)(gridDim.x - 1 - blockIdx.x);  // biggest blocks first
    const int bh = blockIdx.y;
    const int b = bh >> 4;
    const int h = bh & 15;

    const int tid = threadIdx.x;
    const int tx = tid & 15;
    const int ti = tid >> 4;
    const int i0 = ti * 8;
    const int c0 = tx * 4;

    const float gamma = 1.0f - __int_as_float((127 - 5 - h) << 23);
    const float l2g = log2f(gamma);

    const int tq0 = qt * 64;
    const int lr = tid >> 4;
    const int lc = (tid & 15) * 4;

    const float* qbase = g_q + (size_t)(b * TV + tq0) * CV + h * DHV;
#pragma unroll
    for (int l = 0; l < 8; ++l) {
        float4 qv = *(const float4*)(qbase + (size_t)(lr + l * 8) * CV + lc);
        qs[lc + 0][lr + l * 8] = qv.x;
        qs[lc + 1][lr + l * 8] = qv.y;
        qs[lc + 2][lr + l * 8] = qv.z;
        qs[lc + 3][lr + l * 8] = qv.w;
    }

    float o[8][4];
#pragma unroll
    for (int i = 0; i < 8; ++i)
#pragma unroll
        for (int d = 0; d < 4; ++d) o[i][d] = 0.f;

    const float scale = 0.125f;

    for (int kt = 0; kt <= qt; ++kt) {
        const int tk0 = kt * 64;
        const float* kb = g_k + (size_t)(b * TV + tk0) * CV + h * DHV;
        const float* vb = g_v + (size_t)(b * TV + tk0) * CV + h * DHV;

        __syncthreads();
#pragma unroll
        for (int l = 0; l < 8; ++l) {
            float4 kv = *(const float4*)(kb + (size_t)(lr + l * 8) * CV + lc);
            ks[lc + 0][lr + l * 8] = kv.x;
            ks[lc + 1][lr + l * 8] = kv.y;
            ks[lc + 2][lr + l * 8] = kv.z;
            ks[lc + 3][lr + l * 8] = kv.w;
            float4 vv = *(const float4*)(vb + (size_t)(lr + l * 8) * CV + lc);
            *(float4*)(&vs[lr + l * 8][lc]) = vv;
        }
        __syncthreads();

        float s[8][4];
#pragma unroll
        for (int i = 0; i < 8; ++i)
#pragma unroll
            for (int j = 0; j < 4; ++j) s[i][j] = 0.f;

#pragma unroll 16
        for (int d = 0; d < 64; ++d) {
            float4 a0 = *(const float4*)(&qs[d][i0]);
            float4 a1 = *(const float4*)(&qs[d][i0 + 4]);
            float4 bk = *(const float4*)(&ks[d][c0]);
            float av[8] = {a0.x, a0.y, a0.z, a0.w, a1.x, a1.y, a1.z, a1.w};
            float bw[4] = {bk.x, bk.y, bk.z, bk.w};
#pragma unroll
            for (int i = 0; i < 8; ++i)
#pragma unroll
                for (int j = 0; j < 4; ++j)
                    s[i][j] = fmaf(av[i], bw[j], s[i][j]);
        }

        if (kt == qt) {
#pragma unroll
            for (int ii = 0; ii < 8; ++ii)
#pragma unroll
                for (int jj = 0; jj < 4; ++jj) {
                    int dist = (i0 + ii) - (c0 + jj);
                    s[ii][jj] = (dist >= 0)
                        ? s[ii][jj] * scale * fast_exp2((float)dist * l2g)
                        : 0.f;
                }
        } else {
            const int dbase = tq0 - tk0;
#pragma unroll
            for (int ii = 0; ii < 8; ++ii)
#pragma unroll
                for (int jj = 0; jj < 4; ++jj) {
                    float dist = (float)(dbase + (i0 + ii) - (c0 + jj));
                    s[ii][jj] *= scale * fast_exp2(dist * l2g);
                }
        }

        __syncthreads();
#pragma unroll
        for (int jj = 0; jj < 4; ++jj) {
            *(float4*)(&ks[c0 + jj][i0])     = make_float4(s[0][jj], s[1][jj], s[2][jj], s[3][jj]);
            *(float4*)(&ks[c0 + jj][i0 + 4]) = make_float4(s[4][jj], s[5][jj], s[6][jj], s[7][jj]);
        }
        __syncthreads();

#pragma unroll 16
        for (int j = 0; j < 64; ++j) {
            float4 a0 = *(const float4*)(&ks[j][i0]);
            float4 a1 = *(const float4*)(&ks[j][i0 + 4]);
            float4 bv4 = *(const float4*)(&vs[j][c0]);
            float av[8] = {a0.x, a0.y, a0.z, a0.w, a1.x, a1.y, a1.z, a1.w};
            float bw[4] = {bv4.x, bv4.y, bv4.z, bv4.w};
#pragma unroll
            for (int ii = 0; ii < 8; ++ii)
#pragma unroll
                for (int dd = 0; dd < 4; ++dd)
                    o[ii][dd] = fmaf(av[ii], bw[dd], o[ii][dd]);
        }
    }

    float4 gwv = *(const float4*)(gn_w + h * DHV + c0);
    float4 gbv = *(const float4*)(gn_b + h * DHV + c0);
    float wv[4] = {gwv.x, gwv.y, gwv.z, gwv.w};
    float bb[4] = {gbv.x, gbv.y, gbv.z, gbv.w};
    const float invn = 1.0f / 64.0f;

#pragma unroll
    for (int ii = 0; ii < 8; ++ii) {
        float sum = 0.f, sq = 0.f;
#pragma unroll
        for (int dd = 0; dd < 4; ++dd) { sum += o[ii][dd]; sq += o[ii][dd] * o[ii][dd]; }
#pragma unroll
        for (int off = 1; off < 16; off <<= 1) {
            sum += __shfl_xor_sync(0xffffffffu, sum, off);
            sq  += __shfl_xor_sync(0xffffffffu, sq,  off);
        }
        float mean = sum * invn;
        float var = sq * invn - mean * mean;
        float rs = rsqrtf(var + 1e-5f);
        float4 ov;
        ov.x = (o[ii][0] - mean) * rs * wv[0] + bb[0];
        ov.y = (o[ii][1] - mean) * rs * wv[1] + bb[1];
        ov.z = (o[ii][2] - mean) * rs * wv[2] + bb[2];
        ov.w = (o[ii][3] - mean) * rs * wv[3] + bb[3];
        *(float4*)(g_y + (size_t)(b * TV + tq0 + i0 + ii) * CV + h * DHV + c0) = ov;
    }
}

// ---------------------------------------------------------------------------
extern "C" void kernel_launch(void* const* d_in, const int* in_sizes, int n_in,
                              void* d_out, int out_size)
{
    const float* x   = (const float*)d_in[0];
    const float* Wq  = (const float*)d_in[1];
    const float* Wk  = (const float*)d_in[2];
    const float* Wv  = (const float*)d_in[3];
    const float* Wo  = (const float*)d_in[4];
    const float* gnw = (const float*)d_in[5];
    const float* gnb = (const float*)d_in[6];
    float* out = (float*)d_out;

    float *q, *k, *v, *y;
    __nv_bfloat16 *xh, *xl, *wh, *wl, *woh, *wol;
    cudaGetSymbolAddress((void**)&q, g_q);
    cudaGetSymbolAddress((void**)&k, g_k);
    cudaGetSymbolAddress((void**)&v, g_v);
    cudaGetSymbolAddress((void**)&y, g_y);
    cudaGetSymbolAddress((void**)&xh, g_xh);
    cudaGetSymbolAddress((void**)&xl, g_xl);
    cudaGetSymbolAddress((void**)&wh, g_wh);
    cudaGetSymbolAddress((void**)&wl, g_wl);
    cudaGetSymbolAddress((void**)&woh, g_woh);
    cudaGetSymbolAddress((void**)&wol, g_wol);

    cudaFuncSetAttribute(retention_attn,
                         cudaFuncAttributeMaxDynamicSharedMemorySize, (int)SMEM_ATTN);
    cudaFuncSetAttribute(bfgemm,
                         cudaFuncAttributeMaxDynamicSharedMemorySize, GEMM_SMEM);

    const int WN4 = CV * CV / 4;          // 262144
    const int XN4 = MV * CV / 4;          // 1048576

    // 0) hi/lo bf16 splits
    conv_hilo<<<XN4 / 256, 256>>>(x, xh, xl, XN4);
    conv_hilo<<<WN4 / 256, 256>>>(Wq, wh,                   wl,                   WN4);
    conv_hilo<<<WN4 / 256, 256>>>(Wk, wh + (size_t)CV * CV, wl + (size_t)CV * CV, WN4);
    conv_hilo<<<WN4 / 256, 256>>>(Wv, wh + (size_t)2 * CV * CV, wl + (size_t)2 * CV * CV, WN4);
    conv_hilo<<<WN4 / 256, 256>>>(Wo, woh, wol, WN4);

    // 1) QKV projections on tensor cores (one launch, z selects weight/output)
    bfgemm<<<dim3(CV / 128, MV / 128, 3), 256, GEMM_SMEM>>>(xh, xl, wh, wl, q, k, v);
    // 2) RoPE on q,k
    rope_kernel<<<(BV * TV * HV * 32) / 256, 256>>>();
    // 3) Retention + fused GroupNorm -> g_y in (b,t,c) layout
    retention_attn<<<dim3(TV / 64, BV * HV), 128, SMEM_ATTN>>>(gnw, gnb);
    // 4) Output projection: split y, then tensor-core GEMM
    conv_hilo<<<XN4 / 256, 256>>>(y, xh, xl, XN4);
    bfgemm<<<dim3(CV / 128, MV / 128, 1), 256, GEMM_SMEM>>>(xh, xl, woh, wol, out, out, out);
}

// round 6
// speedup vs baseline: 1.6031x; 1.0059x over previous
#include <cuda_runtime.h>
#include <cuda_bf16.h>
#include <math.h>
#include <stdint.h>

#define BV 2
#define TV 2048
#define CV 1024
#define HV 16
#define DHV 64
#define MV (BV * TV)   // 4096

// ---------------------------------------------------------------------------
// Scratch (__device__ globals; allocation-free rule)
// ---------------------------------------------------------------------------
__device__ float g_q[(size_t)MV * CV];
__device__ float g_k[(size_t)MV * CV];
__device__ float g_v[(size_t)MV * CV];
__device__ float g_y[(size_t)MV * CV];

__device__ __nv_bfloat16 g_xh[(size_t)MV * CV];       // x (then y) hi
__device__ __nv_bfloat16 g_xl[(size_t)MV * CV];       // x (then y) lo
__device__ __nv_bfloat16 g_wh[(size_t)3 * CV * CV];   // Wq,Wk,Wv hi
__device__ __nv_bfloat16 g_wl[(size_t)3 * CV * CV];   // Wq,Wk,Wv lo
__device__ __nv_bfloat16 g_woh[(size_t)CV * CV];      // Wo hi
__device__ __nv_bfloat16 g_wol[(size_t)CV * CV];      // Wo lo

// ---------------------------------------------------------------------------
// helpers
// ---------------------------------------------------------------------------
__device__ __forceinline__ uint32_t smem_to_u32(const void* p) {
    uint32_t a;
    asm("{ .reg .u64 t; cvta.to.shared.u64 t, %1; cvt.u32.u64 %0, t; }"
        : "=r"(a) : "l"(p));
    return a;
}

__device__ __forceinline__ void cp16(uint32_t saddr, const void* g) {
    asm volatile("cp.async.cg.shared.global [%0], [%1], 16;"
                 :: "r"(saddr), "l"(g) : "memory");
}
__device__ __forceinline__ void cp_commit() {
    asm volatile("cp.async.commit_group;" ::: "memory");
}
__device__ __forceinline__ void cp_wait1() {
    asm volatile("cp.async.wait_group 1;" ::: "memory");
}
__device__ __forceinline__ void cp_wait0() {
    asm volatile("cp.async.wait_group 0;" ::: "memory");
}

__device__ __forceinline__ void ldsm4(uint32_t& r0, uint32_t& r1,
                                      uint32_t& r2, uint32_t& r3, uint32_t addr) {
    asm volatile("ldmatrix.sync.aligned.m8n8.x4.shared.b16 {%0,%1,%2,%3}, [%4];"
                 : "=r"(r0), "=r"(r1), "=r"(r2), "=r"(r3) : "r"(addr));
}

__device__ __forceinline__ void mma_bf16(float* c, const uint32_t* a, const uint32_t* b) {
    asm volatile(
        "mma.sync.aligned.m16n8k16.row.col.f32.bf16.bf16.f32 "
        "{%0,%1,%2,%3}, {%4,%5,%6,%7}, {%8,%9}, {%0,%1,%2,%3};"
        : "+f"(c[0]), "+f"(c[1]), "+f"(c[2]), "+f"(c[3])
        : "r"(a[0]), "r"(a[1]), "r"(a[2]), "r"(a[3]), "r"(b[0]), "r"(b[1]));
}

__device__ __forceinline__ float fast_exp2(float x) {
    float r;
    asm("ex2.approx.f32 %0, %1;" : "=f"(r) : "f"(x));
    return r;
}

// ---------------------------------------------------------------------------
// fp32 -> (bf16 hi, bf16 lo) split. 4 elements per thread.
// ---------------------------------------------------------------------------
__global__ void conv_hilo(const float* __restrict__ src,
                          __nv_bfloat16* __restrict__ hi,
                          __nv_bfloat16* __restrict__ lo, int n4)
{
    int i = blockIdx.x * blockDim.x + threadIdx.x;
    if (i >= n4) return;
    float4 v = ((const float4*)src)[i];
    __nv_bfloat16 h0 = __float2bfloat16(v.x);
    __nv_bfloat16 h1 = __float2bfloat16(v.y);
    __nv_bfloat16 h2 = __float2bfloat16(v.z);
    __nv_bfloat16 h3 = __float2bfloat16(v.w);
    __nv_bfloat16 l0 = __float2bfloat16(v.x - __bfloat162float(h0));
    __nv_bfloat16 l1 = __float2bfloat16(v.y - __bfloat162float(h1));
    __nv_bfloat16 l2 = __float2bfloat16(v.z - __bfloat162float(h2));
    __nv_bfloat16 l3 = __float2bfloat16(v.w - __bfloat162float(h3));
    ushort4 hv, lv;
    hv.x = __bfloat16_as_ushort(h0); hv.y = __bfloat16_as_ushort(h1);
    hv.z = __bfloat16_as_ushort(h2); hv.w = __bfloat16_as_ushort(h3);
    lv.x = __bfloat16_as_ushort(l0); lv.y = __bfloat16_as_ushort(l1);
    lv.z = __bfloat16_as_ushort(l2); lv.w = __bfloat16_as_ushort(l3);
    ((ushort4*)hi)[i] = hv;
    ((ushort4*)lo)[i] = lv;
}

// ---------------------------------------------------------------------------
// Warp-MMA bf16 GEMM with hi/lo fp32 emulation (mma.sync m16n8k16, HMMA).
// C[M,N] = A[M,K] @ W[N,K]^T via Ah*Wh + Ah*Wl + Al*Wh, fp32 accumulators.
// CTA 128x128, K-chunk 64, 8 warps (4m x 2n), warp tile 32x64.
// SMEM: 2 stages x { Ah, Al, Wh, Wl } tiles of 128 rows x 128 B (SW128 XOR).
// cp.async double-buffered pipeline. grid.z selects among 3 (W, C) pairs.
// ---------------------------------------------------------------------------
#define STAGE_BYTES 65536
#define OFF_AH 0
#define OFF_AL 16384
#define OFF_BH 32768
#define OFF_BL 49152
#define GEMM_SMEM (2 * STAGE_BYTES)

__global__ __launch_bounds__(256)
void bfgemm(const __nv_bfloat16* __restrict__ Ah,
            const __nv_bfloat16* __restrict__ Al,
            const __nv_bfloat16* __restrict__ Wh0,
            const __nv_bfloat16* __restrict__ Wl0,
            float* __restrict__ C0, float* __restrict__ C1, float* __restrict__ C2)
{
    extern __shared__ char smem[];
    const uint32_t sb = smem_to_u32(smem);
    const int tid = threadIdx.x;
    const int wid = tid >> 5;
    const int lane = tid & 31;
    const int z = blockIdx.z;

    const __nv_bfloat16* Wh = Wh0 + (size_t)z * CV * CV;
    const __nv_bfloat16* Wl = Wl0 + (size_t)z * CV * CV;
    float* C = (z == 0) ? C0 : ((z == 1) ? C1 : C2);

    const int bm = blockIdx.y * 128;
    const int bn = blockIdx.x * 128;
    const int warp_m = wid >> 1;       // 0..3 -> 32-row slab
    const int warp_n = wid & 1;        // 0..1 -> 64-col slab

    // loader: 1024 16B-chunks per tile, 4 per thread per matrix
    const int l_row = tid >> 1;                   // unused helper removed
    (void)l_row;

    float c[2][8][4];
#pragma unroll
    for (int mb = 0; mb < 2; ++mb)
#pragma unroll
        for (int nb = 0; nb < 8; ++nb)
#pragma unroll
            for (int e = 0; e < 4; ++e) c[mb][nb][e] = 0.f;

    // ---- issue loads of chunk ch into stage ----
    auto issue = [&](int ch, int stage) {
        const int kc0 = ch * 64;                 // element k offset
        const uint32_t base = sb + stage * STAGE_BYTES;
#pragma unroll
        for (int it = 0; it < 4; ++it) {
            const int idx = it * 256 + tid;      // 0..1023
            const int row = idx >> 3;            // 0..127
            const int colb = (idx & 7) * 16;     // byte col within 128B row
            const uint32_t sw = (uint32_t)(row * 128 + (colb ^ ((row & 7) << 4)));
            const size_t gA = (size_t)(bm + row) * CV + kc0 + (colb >> 1);
            const size_t gB = (size_t)(bn + row) * CV + kc0 + (colb >> 1);
            cp16(base + OFF_AH + sw, Ah + gA);
            cp16(base + OFF_AL + sw, Al + gA);
            cp16(base + OFF_BH + sw, Wh + gB);
            cp16(base + OFF_BL + sw, Wl + gB);
        }
        cp_commit();
    };

    issue(0, 0);

    // per-lane ldmatrix row/col selectors
    const int a_row16 = lane & 15;                 // row within 16
    const int a_koffb = ((lane >> 4) & 1) * 16;    // 0 or 16 bytes (k half)
    const int b_rowsel = (lane & 7) + ((lane >> 4) & 1) * 8;  // row within 16
    const int b_koffb = ((lane >> 3) & 1) * 16;

    const int NT = 16;
    for (int ch = 0; ch < NT; ++ch) {
        if (ch + 1 < NT) issue(ch + 1, (ch + 1) & 1);
        if (ch + 1 < NT) cp_wait1(); else cp_wait0();
        __syncthreads();

        const uint32_t base = sb + (ch & 1) * STAGE_BYTES;
#pragma unroll
        for (int ks = 0; ks < 4; ++ks) {
            const int kb = ks * 32;                // bytes into the 128B row

            uint32_t ah[2][4], al[2][4];
#pragma unroll
            for (int mb = 0; mb < 2; ++mb) {
                const int r = warp_m * 32 + mb * 16 + a_row16;
                const uint32_t ad = base + (uint32_t)(r * 128 +
                                     ((kb + a_koffb) ^ ((r & 7) << 4)));
                ldsm4(ah[mb][0], ah[mb][1], ah[mb][2], ah[mb][3], ad + OFF_AH);
                ldsm4(al[mb][0], al[mb][1], al[mb][2], al[mb][3], ad + OFF_AL);
            }

            uint32_t bh[8][2], bl[8][2];
#pragma unroll
            for (int nq = 0; nq < 4; ++nq) {
                const int r = warp_n * 64 + nq * 16 + b_rowsel;
                const uint32_t bd = base + (uint32_t)(r * 128 +
                                     ((kb + b_koffb) ^ ((r & 7) << 4)));
                uint32_t t0, t1, t2, t3;
                ldsm4(t0, t1, t2, t3, bd + OFF_BH);
                bh[nq * 2][0] = t0; bh[nq * 2][1] = t1;
                bh[nq * 2 + 1][0] = t2; bh[nq * 2 + 1][1] = t3;
                ldsm4(t0, t1, t2, t3, bd + OFF_BL);
                bl[nq * 2][0] = t0; bl[nq * 2][1] = t1;
                bl[nq * 2 + 1][0] = t2; bl[nq * 2 + 1][1] = t3;
            }

#pragma unroll
            for (int mb = 0; mb < 2; ++mb)
#pragma unroll
                for (int nb = 0; nb < 8; ++nb) {
                    mma_bf16(c[mb][nb], ah[mb], bh[nb]);
                    mma_bf16(c[mb][nb], ah[mb], bl[nb]);
                    mma_bf16(c[mb][nb], al[mb], bh[nb]);
                }
        }
        __syncthreads();
    }

    // epilogue: fragment -> global (float2 stores)
    const int gr = lane >> 2;
    const int gc = (lane & 3) * 2;
#pragma unroll
    for (int mb = 0; mb < 2; ++mb) {
        const int row0 = bm + warp_m * 32 + mb * 16 + gr;
#pragma unroll
        for (int nb = 0; nb < 8; ++nb) {
            const int col = bn + warp_n * 64 + nb * 8 + gc;
            *(float2*)(C + (size_t)row0 * CV + col) =
                make_float2(c[mb][nb][0], c[mb][nb][1]);
            *(float2*)(C + (size_t)(row0 + 8) * CV + col) =
                make_float2(c[mb][nb][2], c[mb][nb][3]);
        }
    }
}

// ---------------------------------------------------------------------------
// RoPE on q and k, in place. One thread per (b,t,h,j<32) rotates pair (j, j+32).
// ---------------------------------------------------------------------------
__global__ void rope_kernel()
{
    const int idx = blockIdx.x * blockDim.x + threadIdx.x;   // exactly B*T*H*32
    const int j = idx & 31;
    const int h = (idx >> 5) & (HV - 1);
    const int t = (idx >> 9) & (TV - 1);
    const int b = idx >> 20;

    const float L2_10000 = 13.287712379549449f;
    const float invf = exp2f(-(float)j * (L2_10000 / 32.0f));  // 10000^{-j/32}
    const float ang = (float)t * invf;
    float sn, cs;
    sincosf(ang, &sn, &cs);

    const size_t base = (size_t)(b * TV + t) * CV + h * DHV + j;
    float q1 = g_q[base], q2 = g_q[base + 32];
    g_q[base]      = q1 * cs - q2 * sn;
    g_q[base + 32] = q2 * cs + q1 * sn;
    float k1 = g_k[base], k2 = g_k[base + 32];
    g_k[base]      = k1 * cs - k2 * sn;
    g_k[base + 32] = k2 * cs + k1 * sn;
}

// ---------------------------------------------------------------------------
// Retention attention + fused GroupNorm epilogue (unchanged from R2 PASS).
// ---------------------------------------------------------------------------
#define ATTN_STRIDE 68
#define SMEM_ATTN ((2 * 64 * ATTN_STRIDE + 64 * 64) * sizeof(float))

__global__ __launch_bounds__(128)
void retention_attn(const float* __restrict__ gn_w, const float* __restrict__ gn_b)
{
    extern __shared__ float smemf[];
    float (*qs)[ATTN_STRIDE] = (float(*)[ATTN_STRIDE])(smemf);
    float (*ks)[ATTN_STRIDE] = (float(*)[ATTN_STRIDE])(smemf + 64 * ATTN_STRIDE);
    float (*vs)[64] = (float(*)[64])(smemf + 2 * 64 * ATTN_STRIDE);

    const int qt = (int)(gridDim.x - 1 - blockIdx.x);  // biggest blocks first
    const int bh = blockIdx.y;
    const int b = bh >> 4;
    const int h = bh & 15;

    const int tid = threadIdx.x;
    const int tx = tid & 15;
    const int ti = tid >> 4;
    const int i0 = ti * 8;
    const int c0 = tx * 4;

    const float gamma = 1.0f - __int_as_float((127 - 5 - h) << 23);
    const float l2g = log2f(gamma);

    const int tq0 = qt * 64;
    const int lr = tid >> 4;
    const int lc = (tid & 15) * 4;

    const float* qbase = g_q + (size_t)(b * TV + tq0) * CV + h * DHV;
#pragma unroll
    for (int l = 0; l < 8; ++l) {
        float4 qv = *(const float4*)(qbase + (size_t)(lr + l * 8) * CV + lc);
        qs[lc + 0][lr + l * 8] = qv.x;
        qs[lc + 1][lr + l * 8] = qv.y;
        qs[lc + 2][lr + l * 8] = qv.z;
        qs[lc + 3][lr + l * 8] = qv.w;
    }

    float o[8][4];
#pragma unroll
    for (int i = 0; i < 8; ++i)
#pragma unroll
        for (int d = 0; d < 4; ++d) o[i][d] = 0.f;

    const float scale = 0.125f;

    for (int kt = 0; kt <= qt; ++kt) {
        const int tk0 = kt * 64;
        const float* kb = g_k + (size_t)(b * TV + tk0) * CV + h * DHV;
        const float* vb = g_v + (size_t)(b * TV + tk0) * CV + h * DHV;

        __syncthreads();
#pragma unroll
        for (int l = 0; l < 8; ++l) {
            float4 kv = *(const float4*)(kb + (size_t)(lr + l * 8) * CV + lc);
            ks[lc + 0][lr + l * 8] = kv.x;
            ks[lc + 1][lr + l * 8] = kv.y;
            ks[lc + 2][lr + l * 8] = kv.z;
            ks[lc + 3][lr + l * 8] = kv.w;
            float4 vv = *(const float4*)(vb + (size_t)(lr + l * 8) * CV + lc);
            *(float4*)(&vs[lr + l * 8][lc]) = vv;
        }
        __syncthreads();

        float s[8][4];
#pragma unroll
        for (int i = 0; i < 8; ++i)
#pragma unroll
            for (int j = 0; j < 4; ++j) s[i][j] = 0.f;

#pragma unroll 16
        for (int d = 0; d < 64; ++d) {
            float4 a0 = *(const float4*)(&qs[d][i0]);
            float4 a1 = *(const float4*)(&qs[d][i0 + 4]);
            float4 bk = *(const float4*)(&ks[d][c0]);
            float av[8] = {a0.x, a0.y, a0.z, a0.w, a1.x, a1.y, a1.z, a1.w};
            float bw[4] = {bk.x, bk.y, bk.z, bk.w};
#pragma unroll
            for (int i = 0; i < 8; ++i)
#pragma unroll
                for (int j = 0; j < 4; ++j)
                    s[i][j] = fmaf(av[i], bw[j], s[i][j]);
        }

        if (kt == qt) {
#pragma unroll
            for (int ii = 0; ii < 8; ++ii)
#pragma unroll
                for (int jj = 0; jj < 4; ++jj) {
                    int dist = (i0 + ii) - (c0 + jj);
                    s[ii][jj] = (dist >= 0)
                        ? s[ii][jj] * scale * fast_exp2((float)dist * l2g)
                        : 0.f;
                }
        } else {
            const int dbase = tq0 - tk0;
#pragma unroll
            for (int ii = 0; ii < 8; ++ii)
#pragma unroll
                for (int jj = 0; jj < 4; ++jj) {
                    float dist = (float)(dbase + (i0 + ii) - (c0 + jj));
                    s[ii][jj] *= scale * fast_exp2(dist * l2g);
                }
        }

        __syncthreads();
#pragma unroll
        for (int jj = 0; jj < 4; ++jj) {
            *(float4*)(&ks[c0 + jj][i0])     = make_float4(s[0][jj], s[1][jj], s[2][jj], s[3][jj]);
            *(float4*)(&ks[c0 + jj][i0 + 4]) = make_float4(s[4][jj], s[5][jj], s[6][jj], s[7][jj]);
        }
        __syncthreads();

#pragma unroll 16
        for (int j = 0; j < 64; ++j) {
            float4 a0 = *(const float4*)(&ks[j][i0]);
            float4 a1 = *(const float4*)(&ks[j][i0 + 4]);
            float4 bv4 = *(const float4*)(&vs[j][c0]);
            float av[8] = {a0.x, a0.y, a0.z, a0.w, a1.x, a1.y, a1.z, a1.w};
            float bw[4] = {bv4.x, bv4.y, bv4.z, bv4.w};
#pragma unroll
            for (int ii = 0; ii < 8; ++ii)
#pragma unroll
                for (int dd = 0; dd < 4; ++dd)
                    o[ii][dd] = fmaf(av[ii], bw[dd], o[ii][dd]);
        }
    }

    float4 gwv = *(const float4*)(gn_w + h * DHV + c0);
    float4 gbv = *(const float4*)(gn_b + h * DHV + c0);
    float wv[4] = {gwv.x, gwv.y, gwv.z, gwv.w};
    float bb[4] = {gbv.x, gbv.y, gbv.z, gbv.w};
    const float invn = 1.0f / 64.0f;

#pragma unroll
    for (int ii = 0; ii < 8; ++ii) {
        float sum = 0.f, sq = 0.f;
#pragma unroll
        for (int dd = 0; dd < 4; ++dd) { sum += o[ii][dd]; sq += o[ii][dd] * o[ii][dd]; }
#pragma unroll
        for (int off = 1; off < 16; off <<= 1) {
            sum += __shfl_xor_sync(0xffffffffu, sum, off);
            sq  += __shfl_xor_sync(0xffffffffu, sq,  off);
        }
        float mean = sum * invn;
        float var = sq * invn - mean * mean;
        float rs = rsqrtf(var + 1e-5f);
        float4 ov;
        ov.x = (o[ii][0] - mean) * rs * wv[0] + bb[0];
        ov.y = (o[ii][1] - mean) * rs * wv[1] + bb[1];
        ov.z = (o[ii][2] - mean) * rs * wv[2] + bb[2];
        ov.w = (o[ii][3] - mean) * rs * wv[3] + bb[3];
        *(float4*)(g_y + (size_t)(b * TV + tq0 + i0 + ii) * CV + h * DHV + c0) = ov;
    }
}

// ---------------------------------------------------------------------------
extern "C" void kernel_launch(void* const* d_in, const int* in_sizes, int n_in,
                              void* d_out, int out_size)
{
    const float* x   = (const float*)d_in[0];
    const float* Wq  = (const float*)d_in[1];
    const float* Wk  = (const float*)d_in[2];
    const float* Wv  = (const float*)d_in[3];
    const float* Wo  = (const float*)d_in[4];
    const float* gnw = (const float*)d_in[5];
    const float* gnb = (const float*)d_in[6];
    float* out = (float*)d_out;

    float *q, *k, *v, *y;
    __nv_bfloat16 *xh, *xl, *wh, *wl, *woh, *wol;
    cudaGetSymbolAddress((void**)&q, g_q);
    cudaGetSymbolAddress((void**)&k, g_k);
    cudaGetSymbolAddress((void**)&v, g_v);
    cudaGetSymbolAddress((void**)&y, g_y);
    cudaGetSymbolAddress((void**)&xh, g_xh);
    cudaGetSymbolAddress((void**)&xl, g_xl);
    cudaGetSymbolAddress((void**)&wh, g_wh);
    cudaGetSymbolAddress((void**)&wl, g_wl);
    cudaGetSymbolAddress((void**)&woh, g_woh);
    cudaGetSymbolAddress((void**)&wol, g_wol);

    cudaFuncSetAttribute(retention_attn,
                         cudaFuncAttributeMaxDynamicSharedMemorySize, (int)SMEM_ATTN);
    cudaFuncSetAttribute(bfgemm,
                         cudaFuncAttributeMaxDynamicSharedMemorySize, GEMM_SMEM);

    const int WN4 = CV * CV / 4;          // 262144
    const int XN4 = MV * CV / 4;          // 1048576

    // 0) hi/lo bf16 splits
    conv_hilo<<<XN4 / 256, 256>>>(x, xh, xl, XN4);
    conv_hilo<<<WN4 / 256, 256>>>(Wq, wh,                   wl,                   WN4);
    conv_hilo<<<WN4 / 256, 256>>>(Wk, wh + (size_t)CV * CV, wl + (size_t)CV * CV, WN4);
    conv_hilo<<<WN4 / 256, 256>>>(Wv, wh + (size_t)2 * CV * CV, wl + (size_t)2 * CV * CV, WN4);
    conv_hilo<<<WN4 / 256, 256>>>(Wo, woh, wol, WN4);

    // 1) QKV projections on tensor cores (one launch, z selects weight/output)
    bfgemm<<<dim3(CV / 128, MV / 128, 3), 256, GEMM_SMEM>>>(xh, xl, wh, wl, q, k, v);
    // 2) RoPE on q,k
    rope_kernel<<<(BV * TV * HV * 32) / 256, 256>>>();
    // 3) Retention + fused GroupNorm -> g_y in (b,t,c) layout
    retention_attn<<<dim3(TV / 64, BV * HV), 128, SMEM_ATTN>>>(gnw, gnb);
    // 4) Output projection: split y, then tensor-core GEMM
    conv_hilo<<<XN4 / 256, 256>>>(y, xh, xl, XN4);
    bfgemm<<<dim3(CV / 128, MV / 128, 1), 256, GEMM_SMEM>>>(xh, xl, woh, wol, out, out, out);
}

// round 7
// speedup vs baseline: 2.9920x; 1.8663x over previous
#include <cuda_runtime.h>
#include <cuda_bf16.h>
#include <math.h>
#include <stdint.h>

#define BV 2
#define TV 2048
#define CV 1024
#define HV 16
#define DHV 64
#define MV (BV * TV)   // 4096

// ---------------------------------------------------------------------------
// Scratch (__device__ globals; allocation-free rule)
// ---------------------------------------------------------------------------
__device__ float g_q[(size_t)MV * CV];
__device__ float g_k[(size_t)MV * CV];
__device__ float g_v[(size_t)MV * CV];

__device__ __nv_bfloat16 g_xh[(size_t)MV * CV];       // x (then normed out) hi
__device__ __nv_bfloat16 g_xl[(size_t)MV * CV];       // x (then normed out) lo
__device__ __nv_bfloat16 g_wh[(size_t)3 * CV * CV];   // Wq,Wk,Wv hi
__device__ __nv_bfloat16 g_wl[(size_t)3 * CV * CV];   // Wq,Wk,Wv lo
__device__ __nv_bfloat16 g_woh[(size_t)CV * CV];      // Wo hi
__device__ __nv_bfloat16 g_wol[(size_t)CV * CV];      // Wo lo

__device__ __nv_bfloat16 g_qh[(size_t)MV * CV];       // roped q hi/lo  [b*T+t][h*64+d]
__device__ __nv_bfloat16 g_ql[(size_t)MV * CV];
__device__ __nv_bfloat16 g_kh[(size_t)MV * CV];       // roped k hi/lo
__device__ __nv_bfloat16 g_kl[(size_t)MV * CV];
__device__ __nv_bfloat16 g_vth[(size_t)MV * CV];      // v^T hi/lo  [bh][d][t]
__device__ __nv_bfloat16 g_vtl[(size_t)MV * CV];

// ---------------------------------------------------------------------------
// helpers
// ---------------------------------------------------------------------------
__device__ __forceinline__ uint32_t smem_to_u32(const void* p) {
    uint32_t a;
    asm("{ .reg .u64 t; cvta.to.shared.u64 t, %1; cvt.u32.u64 %0, t; }"
        : "=r"(a) : "l"(p));
    return a;
}
__device__ __forceinline__ void cp16(uint32_t saddr, const void* g) {
    asm volatile("cp.async.cg.shared.global [%0], [%1], 16;"
                 :: "r"(saddr), "l"(g) : "memory");
}
__device__ __forceinline__ void cp_commit() {
    asm volatile("cp.async.commit_group;" ::: "memory");
}
__device__ __forceinline__ void cp_wait1() {
    asm volatile("cp.async.wait_group 1;" ::: "memory");
}
__device__ __forceinline__ void cp_wait0() {
    asm volatile("cp.async.wait_group 0;" ::: "memory");
}
__device__ __forceinline__ void ldsm4(uint32_t& r0, uint32_t& r1,
                                      uint32_t& r2, uint32_t& r3, uint32_t addr) {
    asm volatile("ldmatrix.sync.aligned.m8n8.x4.shared.b16 {%0,%1,%2,%3}, [%4];"
                 : "=r"(r0), "=r"(r1), "=r"(r2), "=r"(r3) : "r"(addr));
}
__device__ __forceinline__ void mma_bf16(float* c, const uint32_t* a, const uint32_t* b) {
    asm volatile(
        "mma.sync.aligned.m16n8k16.row.col.f32.bf16.bf16.f32 "
        "{%0,%1,%2,%3}, {%4,%5,%6,%7}, {%8,%9}, {%0,%1,%2,%3};"
        : "+f"(c[0]), "+f"(c[1]), "+f"(c[2]), "+f"(c[3])
        : "r"(a[0]), "r"(a[1]), "r"(a[2]), "r"(a[3]), "r"(b[0]), "r"(b[1]));
}
__device__ __forceinline__ float fast_exp2(float x) {
    float r;
    asm("ex2.approx.f32 %0, %1;" : "=f"(r) : "f"(x));
    return r;
}
// pack: result = {lo, hi} bf16x2
__device__ __forceinline__ uint32_t pack_bf16(float lo, float hi) {
    uint32_t r;
    asm("cvt.rn.bf16x2.f32 %0, %1, %2;" : "=r"(r) : "f"(hi), "f"(lo));
    return r;
}
__device__ __forceinline__ float bf16lo_f32(uint32_t p) { return __uint_as_float(p << 16); }
__device__ __forceinline__ float bf16hi_f32(uint32_t p) { return __uint_as_float(p & 0xffff0000u); }

// ---------------------------------------------------------------------------
// fp32 -> (bf16 hi, bf16 lo) split. 4 elements per thread.
// ---------------------------------------------------------------------------
__global__ void conv_hilo(const float* __restrict__ src,
                          __nv_bfloat16* __restrict__ hi,
                          __nv_bfloat16* __restrict__ lo, int n4)
{
    int i = blockIdx.x * blockDim.x + threadIdx.x;
    if (i >= n4) return;
    float4 v = ((const float4*)src)[i];
    __nv_bfloat16 h0 = __float2bfloat16(v.x);
    __nv_bfloat16 h1 = __float2bfloat16(v.y);
    __nv_bfloat16 h2 = __float2bfloat16(v.z);
    __nv_bfloat16 h3 = __float2bfloat16(v.w);
    __nv_bfloat16 l0 = __float2bfloat16(v.x - __bfloat162float(h0));
    __nv_bfloat16 l1 = __float2bfloat16(v.y - __bfloat162float(h1));
    __nv_bfloat16 l2 = __float2bfloat16(v.z - __bfloat162float(h2));
    __nv_bfloat16 l3 = __float2bfloat16(v.w - __bfloat162float(h3));
    ushort4 hv, lv;
    hv.x = __bfloat16_as_ushort(h0); hv.y = __bfloat16_as_ushort(h1);
    hv.z = __bfloat16_as_ushort(h2); hv.w = __bfloat16_as_ushort(h3);
    lv.x = __bfloat16_as_ushort(l0); lv.y = __bfloat16_as_ushort(l1);
    lv.z = __bfloat16_as_ushort(l2); lv.w = __bfloat16_as_ushort(l3);
    ((ushort4*)hi)[i] = hv;
    ((ushort4*)lo)[i] = lv;
}

// ---------------------------------------------------------------------------
// Warp-MMA bf16 GEMM with hi/lo fp32 emulation (unchanged from R6 PASS).
// ---------------------------------------------------------------------------
#define STAGE_BYTES 65536
#define OFF_AH 0
#define OFF_AL 16384
#define OFF_BH 32768
#define OFF_BL 49152
#define GEMM_SMEM (2 * STAGE_BYTES)

__global__ __launch_bounds__(256)
void bfgemm(const __nv_bfloat16* __restrict__ Ah,
            const __nv_bfloat16* __restrict__ Al,
            const __nv_bfloat16* __restrict__ Wh0,
            const __nv_bfloat16* __restrict__ Wl0,
            float* __restrict__ C0, float* __restrict__ C1, float* __restrict__ C2)
{
    extern __shared__ char smem[];
    const uint32_t sb = smem_to_u32(smem);
    const int tid = threadIdx.x;
    const int wid = tid >> 5;
    const int lane = tid & 31;
    const int z = blockIdx.z;

    const __nv_bfloat16* Wh = Wh0 + (size_t)z * CV * CV;
    const __nv_bfloat16* Wl = Wl0 + (size_t)z * CV * CV;
    float* C = (z == 0) ? C0 : ((z == 1) ? C1 : C2);

    const int bm = blockIdx.y * 128;
    const int bn = blockIdx.x * 128;
    const int warp_m = wid >> 1;
    const int warp_n = wid & 1;

    float c[2][8][4];
#pragma unroll
    for (int mb = 0; mb < 2; ++mb)
#pragma unroll
        for (int nb = 0; nb < 8; ++nb)
#pragma unroll
            for (int e = 0; e < 4; ++e) c[mb][nb][e] = 0.f;

    auto issue = [&](int ch, int stage) {
        const int kc0 = ch * 64;
        const uint32_t base = sb + stage * STAGE_BYTES;
#pragma unroll
        for (int it = 0; it < 4; ++it) {
            const int idx = it * 256 + tid;
            const int row = idx >> 3;
            const int colb = (idx & 7) * 16;
            const uint32_t sw = (uint32_t)(row * 128 + (colb ^ ((row & 7) << 4)));
            const size_t gA = (size_t)(bm + row) * CV + kc0 + (colb >> 1);
            const size_t gB = (size_t)(bn + row) * CV + kc0 + (colb >> 1);
            cp16(base + OFF_AH + sw, Ah + gA);
            cp16(base + OFF_AL + sw, Al + gA);
            cp16(base + OFF_BH + sw, Wh + gB);
            cp16(base + OFF_BL + sw, Wl + gB);
        }
        cp_commit();
    };

    issue(0, 0);

    const int a_row16 = lane & 15;
    const int a_koffb = ((lane >> 4) & 1) * 16;
    const int b_rowsel = (lane & 7) + ((lane >> 4) & 1) * 8;
    const int b_koffb = ((lane >> 3) & 1) * 16;

    const int NT = 16;
    for (int ch = 0; ch < NT; ++ch) {
        if (ch + 1 < NT) issue(ch + 1, (ch + 1) & 1);
        if (ch + 1 < NT) cp_wait1(); else cp_wait0();
        __syncthreads();

        const uint32_t base = sb + (ch & 1) * STAGE_BYTES;
#pragma unroll
        for (int ks = 0; ks < 4; ++ks) {
            const int kb = ks * 32;

            uint32_t ah[2][4], al[2][4];
#pragma unroll
            for (int mb = 0; mb < 2; ++mb) {
                const int r = warp_m * 32 + mb * 16 + a_row16;
                const uint32_t ad = base + (uint32_t)(r * 128 +
                                     ((kb + a_koffb) ^ ((r & 7) << 4)));
                ldsm4(ah[mb][0], ah[mb][1], ah[mb][2], ah[mb][3], ad + OFF_AH);
                ldsm4(al[mb][0], al[mb][1], al[mb][2], al[mb][3], ad + OFF_AL);
            }

            uint32_t bh[8][2], bl[8][2];
#pragma unroll
            for (int nq = 0; nq < 4; ++nq) {
                const int r = warp_n * 64 + nq * 16 + b_rowsel;
                const uint32_t bd = base + (uint32_t)(r * 128 +
                                     ((kb + b_koffb) ^ ((r & 7) << 4)));
                uint32_t t0, t1, t2, t3;
                ldsm4(t0, t1, t2, t3, bd + OFF_BH);
                bh[nq * 2][0] = t0; bh[nq * 2][1] = t1;
                bh[nq * 2 + 1][0] = t2; bh[nq * 2 + 1][1] = t3;
                ldsm4(t0, t1, t2, t3, bd + OFF_BL);
                bl[nq * 2][0] = t0; bl[nq * 2][1] = t1;
                bl[nq * 2 + 1][0] = t2; bl[nq * 2 + 1][1] = t3;
            }

#pragma unroll
            for (int mb = 0; mb < 2; ++mb)
#pragma unroll
                for (int nb = 0; nb < 8; ++nb) {
                    mma_bf16(c[mb][nb], ah[mb], bh[nb]);
                    mma_bf16(c[mb][nb], ah[mb], bl[nb]);
                    mma_bf16(c[mb][nb], al[mb], bh[nb]);
                }
        }
        __syncthreads();
    }

    const int gr = lane >> 2;
    const int gc = (lane & 3) * 2;
#pragma unroll
    for (int mb = 0; mb < 2; ++mb) {
        const int row0 = bm + warp_m * 32 + mb * 16 + gr;
#pragma unroll
        for (int nb = 0; nb < 8; ++nb) {
            const int col = bn + warp_n * 64 + nb * 8 + gc;
            *(float2*)(C + (size_t)row0 * CV + col) =
                make_float2(c[mb][nb][0], c[mb][nb][1]);
            *(float2*)(C + (size_t)(row0 + 8) * CV + col) =
                make_float2(c[mb][nb][2], c[mb][nb][3]);
        }
    }
}

// ---------------------------------------------------------------------------
// RoPE on q and k + bf16 hi/lo conversion. Thread per (b,t,h,j<32).
// ---------------------------------------------------------------------------
__global__ void rope_conv()
{
    const int idx = blockIdx.x * blockDim.x + threadIdx.x;
    const int j = idx & 31;
    const int h = (idx >> 5) & (HV - 1);
    const int t = (idx >> 9) & (TV - 1);
    const int b = idx >> 20;

    const float L2_10000 = 13.287712379549449f;
    const float invf = exp2f(-(float)j * (L2_10000 / 32.0f));
    const float ang = (float)t * invf;
    float sn, cs;
    sincosf(ang, &sn, &cs);

    const size_t base = (size_t)(b * TV + t) * CV + h * DHV + j;

    float q1 = g_q[base], q2 = g_q[base + 32];
    float qa = q1 * cs - q2 * sn;
    float qb = q2 * cs + q1 * sn;
    float k1 = g_k[base], k2 = g_k[base + 32];
    float ka = k1 * cs - k2 * sn;
    float kb = k2 * cs + k1 * sn;

    __nv_bfloat16 hqa = __float2bfloat16(qa);
    __nv_bfloat16 hqb = __float2bfloat16(qb);
    __nv_bfloat16 hka = __float2bfloat16(ka);
    __nv_bfloat16 hkb = __float2bfloat16(kb);
    g_qh[base]      = hqa;
    g_qh[base + 32] = hqb;
    g_ql[base]      = __float2bfloat16(qa - __bfloat162float(hqa));
    g_ql[base + 32] = __float2bfloat16(qb - __bfloat162float(hqb));
    g_kh[base]      = hka;
    g_kh[base + 32] = hkb;
    g_kl[base]      = __float2bfloat16(ka - __bfloat162float(hka));
    g_kl[base + 32] = __float2bfloat16(kb - __bfloat162float(hkb));
}

// ---------------------------------------------------------------------------
// v transpose + hi/lo: g_v [b*T+t][h*64+d] -> g_vth/g_vtl [bh][d][t].
// Block: (ttile, bh), 256 threads, 64x64 tile via smem.
// ---------------------------------------------------------------------------
__global__ __launch_bounds__(256)
void vtrans()
{
    __shared__ float vt[64][65];
    const int bh = blockIdx.y;
    const int b = bh >> 4, h = bh & 15;
    const int t0 = blockIdx.x * 64;
    const int tid = threadIdx.x;

#pragma unroll
    for (int it = 0; it < 4; ++it) {
        const int idx = it * 256 + tid;      // 1024 float4 slots
        const int row = idx >> 4;            // t within tile
        const int c4 = (idx & 15) * 4;       // d
        float4 v = *(const float4*)(g_v + (size_t)(b * TV + t0 + row) * CV + h * DHV + c4);
        vt[row][c4 + 0] = v.x; vt[row][c4 + 1] = v.y;
        vt[row][c4 + 2] = v.z; vt[row][c4 + 3] = v.w;
    }
    __syncthreads();

#pragma unroll
    for (int it = 0; it < 4; ++it) {
        const int idx = it * 256 + tid;
        const int d = idx >> 4;              // output row
        const int tc = (idx & 15) * 4;       // t chunk
        float x0 = vt[tc + 0][d], x1 = vt[tc + 1][d];
        float x2 = vt[tc + 2][d], x3 = vt[tc + 3][d];
        uint32_t h01 = pack_bf16(x0, x1);
        uint32_t h23 = pack_bf16(x2, x3);
        float r0 = x0 - bf16lo_f32(h01), r1 = x1 - bf16hi_f32(h01);
        float r2 = x2 - bf16lo_f32(h23), r3 = x3 - bf16hi_f32(h23);
        uint32_t l01 = pack_bf16(r0, r1);
        uint32_t l23 = pack_bf16(r2, r3);
        const size_t off = (size_t)(bh * DHV + d) * TV + t0 + tc;
        *(uint2*)(g_vth + off) = make_uint2(h01, h23);
        *(uint2*)(g_vtl + off) = make_uint2(l01, l23);
    }
}

// ---------------------------------------------------------------------------
// Retention attention on tensor cores (bf16 hi/lo, mma.sync m16n8k16) with
// fused GroupNorm epilogue writing bf16 hi/lo into the out-proj input.
// Block: (qt of 64 rows, bh). 4 warps; warp w owns q rows [16w, 16w+16).
// SMEM: qh/ql 8K each, kh/kl 8K, vth/vtl 8K = 48KB. Rows are 128B, XOR swizzle.
// ---------------------------------------------------------------------------
#define AQH 0
#define AQL 8192
#define AKH 16384
#define AKL 24576
#define AVH 32768
#define AVL 40960
#define ATTN_SMEM 49152

__global__ __launch_bounds__(128)
void retention_mma(const float* __restrict__ gn_w, const float* __restrict__ gn_b)
{
    extern __shared__ char smem[];
    const uint32_t sb = smem_to_u32(smem);
    const int tid = threadIdx.x;
    const int w = tid >> 5;
    const int lane = tid & 31;

    const int qt = (int)(gridDim.x - 1 - blockIdx.x);   // big tiles first
    const int bh = blockIdx.y;
    const int b = bh >> 4, h = bh & 15;
    const int tq0 = qt * 64;

    const int g = lane >> 2;        // accumulator row group
    const int t4 = lane & 3;        // accumulator col group

    const float gamma = 1.0f - __int_as_float((127 - 5 - h) << 23);
    const float l2g = log2f(gamma);
    const float ginv1 = fast_exp2(-l2g);
    const float ginv8 = fast_exp2(-8.0f * l2g);
    const float gpow8 = fast_exp2(8.0f * l2g);
    const float ctf = fast_exp2(-2.0f * (float)t4 * l2g);

    // ---- load q tile, build persistent A fragments ----
#pragma unroll
    for (int it = 0; it < 4; ++it) {
        const int idx = it * 128 + tid;
        const int row = idx >> 3;
        const int colb = (idx & 7) * 16;
        const uint32_t sw = (uint32_t)(row * 128 + (colb ^ ((row & 7) << 4)));
        const size_t gq = (size_t)(b * TV + tq0 + row) * CV + h * DHV + (colb >> 1);
        cp16(sb + AQH + sw, g_qh + gq);
        cp16(sb + AQL + sw, g_ql + gq);
    }
    cp_commit(); cp_wait0();
    __syncthreads();

    uint32_t qfh[4][4], qfl[4][4];
    {
        const int ar = w * 16 + (lane & 15);
        const int ak = ((lane >> 4) & 1) * 16;
#pragma unroll
        for (int ks = 0; ks < 4; ++ks) {
            const uint32_t ad = sb + (uint32_t)(ar * 128 + ((ks * 32 + ak) ^ ((ar & 7) << 4)));
            ldsm4(qfh[ks][0], qfh[ks][1], qfh[ks][2], qfh[ks][3], ad + AQH);
            ldsm4(qfl[ks][0], qfl[ks][1], qfl[ks][2], qfl[ks][3], ad + AQL);
        }
    }

    float o[8][4];
#pragma unroll
    for (int nb = 0; nb < 8; ++nb)
#pragma unroll
        for (int e = 0; e < 4; ++e) o[nb][e] = 0.f;

    const int b_row = (lane & 7) + ((lane >> 4) & 1) * 8;
    const int b_koffb = ((lane >> 3) & 1) * 16;

    for (int kt = 0; kt <= qt; ++kt) {
        const int tk0 = kt * 64;

        // load k (hi/lo) and v^T (hi/lo) tiles
#pragma unroll
        for (int it = 0; it < 4; ++it) {
            const int idx = it * 128 + tid;
            const int row = idx >> 3;
            const int colb = (idx & 7) * 16;
            const uint32_t sw = (uint32_t)(row * 128 + (colb ^ ((row & 7) << 4)));
            const size_t gk = (size_t)(b * TV + tk0 + row) * CV + h * DHV + (colb >> 1);
            const size_t gv = (size_t)(bh * DHV + row) * TV + tk0 + (colb >> 1);
            cp16(sb + AKH + sw, g_kh + gk);
            cp16(sb + AKL + sw, g_kl + gk);
            cp16(sb + AVH + sw, g_vth + gv);
            cp16(sb + AVL + sw, g_vtl + gv);
        }
        cp_commit(); cp_wait0();
        __syncthreads();

        // ---- S = q k^T (3-term hi/lo) ----
        float s[8][4];
#pragma unroll
        for (int nb = 0; nb < 8; ++nb)
#pragma unroll
            for (int e = 0; e < 4; ++e) s[nb][e] = 0.f;

#pragma unroll
        for (int ks = 0; ks < 4; ++ks) {
#pragma unroll
            for (int nq = 0; nq < 4; ++nq) {
                const int r = nq * 16 + b_row;
                const uint32_t bd = sb + (uint32_t)(r * 128 +
                                     ((ks * 32 + b_koffb) ^ ((r & 7) << 4)));
                uint32_t h0, h1, h2, h3, l0, l1, l2, l3;
                ldsm4(h0, h1, h2, h3, bd + AKH);
                ldsm4(l0, l1, l2, l3, bd + AKL);
                uint32_t bh0[2] = {h0, h1}, bh1[2] = {h2, h3};
                uint32_t bl0[2] = {l0, l1}, bl1[2] = {l2, l3};
                mma_bf16(s[nq * 2],     qfh[ks], bh0);
                mma_bf16(s[nq * 2],     qfh[ks], bl0);
                mma_bf16(s[nq * 2],     qfl[ks], bh0);
                mma_bf16(s[nq * 2 + 1], qfh[ks], bh1);
                mma_bf16(s[nq * 2 + 1], qfh[ks], bl1);
                mma_bf16(s[nq * 2 + 1], qfl[ks], bh1);
            }
        }

        // ---- decay * scale (factored; 1 MUFU per ktile) ----
        const int dbase = tq0 - tk0;
        const float rf0 = 0.125f * fast_exp2((float)(dbase + w * 16 + g) * l2g);
        const float rf8 = rf0 * gpow8;
        float cf = ctf;
        if (kt < qt) {
#pragma unroll
            for (int nb = 0; nb < 8; ++nb) {
                const float c0f = cf, c1f = cf * ginv1;
                s[nb][0] *= rf0 * c0f;
                s[nb][1] *= rf0 * c1f;
                s[nb][2] *= rf8 * c0f;
                s[nb][3] *= rf8 * c1f;
                cf *= ginv8;
            }
        } else {
            const int r0 = w * 16 + g, r1 = r0 + 8;
#pragma unroll
            for (int nb = 0; nb < 8; ++nb) {
                const int j0 = 8 * nb + 2 * t4;
                const float c0f = cf, c1f = cf * ginv1;
                s[nb][0] = (r0 >= j0)     ? s[nb][0] * rf0 * c0f : 0.f;
                s[nb][1] = (r0 >= j0 + 1) ? s[nb][1] * rf0 * c1f : 0.f;
                s[nb][2] = (r1 >= j0)     ? s[nb][2] * rf8 * c0f : 0.f;
                s[nb][3] = (r1 >= j0 + 1) ? s[nb][3] * rf8 * c1f : 0.f;
                cf *= ginv8;
            }
        }

        // ---- S -> bf16 hi/lo A-fragments (C layout == A layout) ----
        uint32_t sah[4][4], sal[4][4];
#pragma unroll
        for (int kc = 0; kc < 4; ++kc) {
            const int n0 = 2 * kc, n1 = 2 * kc + 1;
            uint32_t p;
            p = pack_bf16(s[n0][0], s[n0][1]);
            sah[kc][0] = p;
            sal[kc][0] = pack_bf16(s[n0][0] - bf16lo_f32(p), s[n0][1] - bf16hi_f32(p));
            p = pack_bf16(s[n0][2], s[n0][3]);
            sah[kc][1] = p;
            sal[kc][1] = pack_bf16(s[n0][2] - bf16lo_f32(p), s[n0][3] - bf16hi_f32(p));
            p = pack_bf16(s[n1][0], s[n1][1]);
            sah[kc][2] = p;
            sal[kc][2] = pack_bf16(s[n1][0] - bf16lo_f32(p), s[n1][1] - bf16hi_f32(p));
            p = pack_bf16(s[n1][2], s[n1][3]);
            sah[kc][3] = p;
            sal[kc][3] = pack_bf16(s[n1][2] - bf16lo_f32(p), s[n1][3] - bf16hi_f32(p));
        }

        // ---- O += S v (3-term hi/lo) ----
#pragma unroll
        for (int kc = 0; kc < 4; ++kc) {
#pragma unroll
            for (int nq = 0; nq < 4; ++nq) {
                const int r = nq * 16 + b_row;
                const uint32_t bd = sb + (uint32_t)(r * 128 +
                                     ((kc * 32 + b_koffb) ^ ((r & 7) << 4)));
                uint32_t h0, h1, h2, h3, l0, l1, l2, l3;
                ldsm4(h0, h1, h2, h3, bd + AVH);
                ldsm4(l0, l1, l2, l3, bd + AVL);
                uint32_t vh0[2] = {h0, h1}, vh1[2] = {h2, h3};
                uint32_t vl0[2] = {l0, l1}, vl1[2] = {l2, l3};
                mma_bf16(o[nq * 2],     sah[kc], vh0);
                mma_bf16(o[nq * 2],     sah[kc], vl0);
                mma_bf16(o[nq * 2],     sal[kc], vh0);
                mma_bf16(o[nq * 2 + 1], sah[kc], vh1);
                mma_bf16(o[nq * 2 + 1], sah[kc], vl1);
                mma_bf16(o[nq * 2 + 1], sal[kc], vh1);
            }
        }
        __syncthreads();   // protect k/v smem before next ktile load
    }

    // ---- fused GroupNorm + bf16 hi/lo store into out-proj input ----
    float sum0 = 0.f, sq0 = 0.f, sum1 = 0.f, sq1 = 0.f;
#pragma unroll
    for (int nb = 0; nb < 8; ++nb) {
        sum0 += o[nb][0] + o[nb][1];
        sq0  += o[nb][0] * o[nb][0] + o[nb][1] * o[nb][1];
        sum1 += o[nb][2] + o[nb][3];
        sq1  += o[nb][2] * o[nb][2] + o[nb][3] * o[nb][3];
    }
#pragma unroll
    for (int off = 1; off < 4; off <<= 1) {
        sum0 += __shfl_xor_sync(0xffffffffu, sum0, off);
        sq0  += __shfl_xor_sync(0xffffffffu, sq0,  off);
        sum1 += __shfl_xor_sync(0xffffffffu, sum1, off);
        sq1  += __shfl_xor_sync(0xffffffffu, sq1,  off);
    }
    const float invn = 1.0f / 64.0f;
    const float mean0 = sum0 * invn;
    const float mean1 = sum1 * invn;
    const float rs0 = rsqrtf(sq0 * invn - mean0 * mean0 + 1e-5f);
    const float rs1 = rsqrtf(sq1 * invn - mean1 * mean1 + 1e-5f);

    const int row0 = tq0 + w * 16 + g;
    const size_t base0 = (size_t)(b * TV + row0) * CV + h * DHV;
    const size_t base1 = base0 + (size_t)8 * CV;

#pragma unroll
    for (int nb = 0; nb < 8; ++nb) {
        const int d0 = 8 * nb + 2 * t4;
        const float2 wv = *(const float2*)(gn_w + h * DHV + d0);
        const float2 bv = *(const float2*)(gn_b + h * DHV + d0);
        float y00 = (o[nb][0] - mean0) * rs0 * wv.x + bv.x;
        float y01 = (o[nb][1] - mean0) * rs0 * wv.y + bv.y;
        float y10 = (o[nb][2] - mean1) * rs1 * wv.x + bv.x;
        float y11 = (o[nb][3] - mean1) * rs1 * wv.y + bv.y;

        uint32_t p0 = pack_bf16(y00, y01);
        uint32_t q0 = pack_bf16(y00 - bf16lo_f32(p0), y01 - bf16hi_f32(p0));
        uint32_t p1 = pack_bf16(y10, y11);
        uint32_t q1 = pack_bf16(y10 - bf16lo_f32(p1), y11 - bf16hi_f32(p1));

        *(uint32_t*)(g_xh + base0 + d0) = p0;
        *(uint32_t*)(g_xl + base0 + d0) = q0;
        *(uint32_t*)(g_xh + base1 + d0) = p1;
        *(uint32_t*)(g_xl + base1 + d0) = q1;
    }
}

// ---------------------------------------------------------------------------
extern "C" void kernel_launch(void* const* d_in, const int* in_sizes, int n_in,
                              void* d_out, int out_size)
{
    const float* x   = (const float*)d_in[0];
    const float* Wq  = (const float*)d_in[1];
    const float* Wk  = (const float*)d_in[2];
    const float* Wv  = (const float*)d_in[3];
    const float* Wo  = (const float*)d_in[4];
    const float* gnw = (const float*)d_in[5];
    const float* gnb = (const float*)d_in[6];
    float* out = (float*)d_out;

    float *q, *k, *v;
    __nv_bfloat16 *xh, *xl, *wh, *wl, *woh, *wol;
    cudaGetSymbolAddress((void**)&q, g_q);
    cudaGetSymbolAddress((void**)&k, g_k);
    cudaGetSymbolAddress((void**)&v, g_v);
    cudaGetSymbolAddress((void**)&xh, g_xh);
    cudaGetSymbolAddress((void**)&xl, g_xl);
    cudaGetSymbolAddress((void**)&wh, g_wh);
    cudaGetSymbolAddress((void**)&wl, g_wl);
    cudaGetSymbolAddress((void**)&woh, g_woh);
    cudaGetSymbolAddress((void**)&wol, g_wol);

    cudaFuncSetAttribute(bfgemm,
                         cudaFuncAttributeMaxDynamicSharedMemorySize, GEMM_SMEM);
    cudaFuncSetAttribute(retention_mma,
                         cudaFuncAttributeMaxDynamicSharedMemorySize, ATTN_SMEM);

    const int WN4 = CV * CV / 4;
    const int XN4 = MV * CV / 4;

    // 0) hi/lo bf16 splits of inputs
    conv_hilo<<<XN4 / 256, 256>>>(x, xh, xl, XN4);
    conv_hilo<<<WN4 / 256, 256>>>(Wq, wh,                       wl,                       WN4);
    conv_hilo<<<WN4 / 256, 256>>>(Wk, wh + (size_t)CV * CV,     wl + (size_t)CV * CV,     WN4);
    conv_hilo<<<WN4 / 256, 256>>>(Wv, wh + (size_t)2 * CV * CV, wl + (size_t)2 * CV * CV, WN4);
    conv_hilo<<<WN4 / 256, 256>>>(Wo, woh, wol, WN4);

    // 1) QKV projections (tensor cores)
    bfgemm<<<dim3(CV / 128, MV / 128, 3), 256, GEMM_SMEM>>>(xh, xl, wh, wl, q, k, v);
    // 2) RoPE + bf16 hi/lo q,k
    rope_conv<<<(BV * TV * HV * 32) / 256, 256>>>();
    // 3) v transpose + hi/lo
    vtrans<<<dim3(TV / 64, BV * HV), 256>>>();
    // 4) Retention on tensor cores + fused GroupNorm -> g_xh/g_xl
    retention_mma<<<dim3(TV / 64, BV * HV), 128, ATTN_SMEM>>>(gnw, gnb);
    // 5) Output projection (tensor cores)
    bfgemm<<<dim3(CV / 128, MV / 128, 1), 256, GEMM_SMEM>>>(xh, xl, woh, wol, out, out, out);
}

// round 8
// speedup vs baseline: 2.9945x; 1.0008x over previous
#include <cuda_runtime.h>
#include <cuda_bf16.h>
#include <math.h>
#include <stdint.h>

#define BV 2
#define TV 2048
#define CV 1024
#define HV 16
#define DHV 64
#define MV (BV * TV)   // 4096

// ---------------------------------------------------------------------------
// Scratch (__device__ globals; allocation-free rule)
// ---------------------------------------------------------------------------
__device__ float g_q[(size_t)MV * CV];
__device__ float g_k[(size_t)MV * CV];
__device__ float g_v[(size_t)MV * CV];

__device__ __nv_bfloat16 g_xh[(size_t)MV * CV];       // x (then normed out) hi
__device__ __nv_bfloat16 g_xl[(size_t)MV * CV];       // x (then normed out) lo
__device__ __nv_bfloat16 g_wh[(size_t)3 * CV * CV];   // Wq,Wk,Wv hi
__device__ __nv_bfloat16 g_wl[(size_t)3 * CV * CV];   // Wq,Wk,Wv lo
__device__ __nv_bfloat16 g_woh[(size_t)CV * CV];      // Wo hi
__device__ __nv_bfloat16 g_wol[(size_t)CV * CV];      // Wo lo

__device__ __nv_bfloat16 g_qh[(size_t)MV * CV];       // roped q hi/lo  [b*T+t][h*64+d]
__device__ __nv_bfloat16 g_ql[(size_t)MV * CV];
__device__ __nv_bfloat16 g_kh[(size_t)MV * CV];       // roped k hi/lo
__device__ __nv_bfloat16 g_kl[(size_t)MV * CV];
__device__ __nv_bfloat16 g_vth[(size_t)MV * CV];      // v^T hi/lo  [bh][d][t]
__device__ __nv_bfloat16 g_vtl[(size_t)MV * CV];

// ---------------------------------------------------------------------------
// helpers
// ---------------------------------------------------------------------------
__device__ __forceinline__ uint32_t smem_to_u32(const void* p) {
    uint32_t a;
    asm("{ .reg .u64 t; cvta.to.shared.u64 t, %1; cvt.u32.u64 %0, t; }"
        : "=r"(a) : "l"(p));
    return a;
}
__device__ __forceinline__ void cp16(uint32_t saddr, const void* g) {
    asm volatile("cp.async.cg.shared.global [%0], [%1], 16;"
                 :: "r"(saddr), "l"(g) : "memory");
}
__device__ __forceinline__ void cp_commit() {
    asm volatile("cp.async.commit_group;" ::: "memory");
}
__device__ __forceinline__ void cp_wait1() {
    asm volatile("cp.async.wait_group 1;" ::: "memory");
}
__device__ __forceinline__ void cp_wait0() {
    asm volatile("cp.async.wait_group 0;" ::: "memory");
}
__device__ __forceinline__ void ldsm4(uint32_t& r0, uint32_t& r1,
                                      uint32_t& r2, uint32_t& r3, uint32_t addr) {
    asm volatile("ldmatrix.sync.aligned.m8n8.x4.shared.b16 {%0,%1,%2,%3}, [%4];"
                 : "=r"(r0), "=r"(r1), "=r"(r2), "=r"(r3) : "r"(addr));
}
__device__ __forceinline__ void mma_bf16(float* c, const uint32_t* a, const uint32_t* b) {
    asm volatile(
        "mma.sync.aligned.m16n8k16.row.col.f32.bf16.bf16.f32 "
        "{%0,%1,%2,%3}, {%4,%5,%6,%7}, {%8,%9}, {%0,%1,%2,%3};"
        : "+f"(c[0]), "+f"(c[1]), "+f"(c[2]), "+f"(c[3])
        : "r"(a[0]), "r"(a[1]), "r"(a[2]), "r"(a[3]), "r"(b[0]), "r"(b[1]));
}
__device__ __forceinline__ float fast_exp2(float x) {
    float r;
    asm("ex2.approx.f32 %0, %1;" : "=f"(r) : "f"(x));
    return r;
}
// pack: result = {lo, hi} bf16x2
__device__ __forceinline__ uint32_t pack_bf16(float lo, float hi) {
    uint32_t r;
    asm("cvt.rn.bf16x2.f32 %0, %1, %2;" : "=r"(r) : "f"(hi), "f"(lo));
    return r;
}
__device__ __forceinline__ float bf16lo_f32(uint32_t p) { return __uint_as_float(p << 16); }
__device__ __forceinline__ float bf16hi_f32(uint32_t p) { return __uint_as_float(p & 0xffff0000u); }

// ---------------------------------------------------------------------------
// fp32 -> (bf16 hi, bf16 lo) split. 4 elements per thread.
// ---------------------------------------------------------------------------
__global__ void conv_hilo(const float* __restrict__ src,
                          __nv_bfloat16* __restrict__ hi,
                          __nv_bfloat16* __restrict__ lo, int n4)
{
    int i = blockIdx.x * blockDim.x + threadIdx.x;
    if (i >= n4) return;
    float4 v = ((const float4*)src)[i];
    __nv_bfloat16 h0 = __float2bfloat16(v.x);
    __nv_bfloat16 h1 = __float2bfloat16(v.y);
    __nv_bfloat16 h2 = __float2bfloat16(v.z);
    __nv_bfloat16 h3 = __float2bfloat16(v.w);
    __nv_bfloat16 l0 = __float2bfloat16(v.x - __bfloat162float(h0));
    __nv_bfloat16 l1 = __float2bfloat16(v.y - __bfloat162float(h1));
    __nv_bfloat16 l2 = __float2bfloat16(v.z - __bfloat162float(h2));
    __nv_bfloat16 l3 = __float2bfloat16(v.w - __bfloat162float(h3));
    ushort4 hv, lv;
    hv.x = __bfloat16_as_ushort(h0); hv.y = __bfloat16_as_ushort(h1);
    hv.z = __bfloat16_as_ushort(h2); hv.w = __bfloat16_as_ushort(h3);
    lv.x = __bfloat16_as_ushort(l0); lv.y = __bfloat16_as_ushort(l1);
    lv.z = __bfloat16_as_ushort(l2); lv.w = __bfloat16_as_ushort(l3);
    ((ushort4*)hi)[i] = hv;
    ((ushort4*)lo)[i] = lv;
}

// ---------------------------------------------------------------------------
// Warp-MMA bf16 GEMM with hi/lo fp32 emulation (unchanged from R6 PASS).
// ---------------------------------------------------------------------------
#define STAGE_BYTES 65536
#define OFF_AH 0
#define OFF_AL 16384
#define OFF_BH 32768
#define OFF_BL 49152
#define GEMM_SMEM (2 * STAGE_BYTES)

__global__ __launch_bounds__(256)
void bfgemm(const __nv_bfloat16* __restrict__ Ah,
            const __nv_bfloat16* __restrict__ Al,
            const __nv_bfloat16* __restrict__ Wh0,
            const __nv_bfloat16* __restrict__ Wl0,
            float* __restrict__ C0, float* __restrict__ C1, float* __restrict__ C2)
{
    extern __shared__ char smem[];
    const uint32_t sb = smem_to_u32(smem);
    const int tid = threadIdx.x;
    const int wid = tid >> 5;
    const int lane = tid & 31;
    const int z = blockIdx.z;

    const __nv_bfloat16* Wh = Wh0 + (size_t)z * CV * CV;
    const __nv_bfloat16* Wl = Wl0 + (size_t)z * CV * CV;
    float* C = (z == 0) ? C0 : ((z == 1) ? C1 : C2);

    const int bm = blockIdx.y * 128;
    const int bn = blockIdx.x * 128;
    const int warp_m = wid >> 1;
    const int warp_n = wid & 1;

    float c[2][8][4];
#pragma unroll
    for (int mb = 0; mb < 2; ++mb)
#pragma unroll
        for (int nb = 0; nb < 8; ++nb)
#pragma unroll
            for (int e = 0; e < 4; ++e) c[mb][nb][e] = 0.f;

    auto issue = [&](int ch, int stage) {
        const int kc0 = ch * 64;
        const uint32_t base = sb + stage * STAGE_BYTES;
#pragma unroll
        for (int it = 0; it < 4; ++it) {
            const int idx = it * 256 + tid;
            const int row = idx >> 3;
            const int colb = (idx & 7) * 16;
            const uint32_t sw = (uint32_t)(row * 128 + (colb ^ ((row & 7) << 4)));
            const size_t gA = (size_t)(bm + row) * CV + kc0 + (colb >> 1);
            const size_t gB = (size_t)(bn + row) * CV + kc0 + (colb >> 1);
            cp16(base + OFF_AH + sw, Ah + gA);
            cp16(base + OFF_AL + sw, Al + gA);
            cp16(base + OFF_BH + sw, Wh + gB);
            cp16(base + OFF_BL + sw, Wl + gB);
        }
        cp_commit();
    };

    issue(0, 0);

    const int a_row16 = lane & 15;
    const int a_koffb = ((lane >> 4) & 1) * 16;
    const int b_rowsel = (lane & 7) + ((lane >> 4) & 1) * 8;
    const int b_koffb = ((lane >> 3) & 1) * 16;

    const int NT = 16;
    for (int ch = 0; ch < NT; ++ch) {
        if (ch + 1 < NT) issue(ch + 1, (ch + 1) & 1);
        if (ch + 1 < NT) cp_wait1(); else cp_wait0();
        __syncthreads();

        const uint32_t base = sb + (ch & 1) * STAGE_BYTES;
#pragma unroll
        for (int ks = 0; ks < 4; ++ks) {
            const int kb = ks * 32;

            uint32_t ah[2][4], al[2][4];
#pragma unroll
            for (int mb = 0; mb < 2; ++mb) {
                const int r = warp_m * 32 + mb * 16 + a_row16;
                const uint32_t ad = base + (uint32_t)(r * 128 +
                                     ((kb + a_koffb) ^ ((r & 7) << 4)));
                ldsm4(ah[mb][0], ah[mb][1], ah[mb][2], ah[mb][3], ad + OFF_AH);
                ldsm4(al[mb][0], al[mb][1], al[mb][2], al[mb][3], ad + OFF_AL);
            }

            uint32_t bh[8][2], bl[8][2];
#pragma unroll
            for (int nq = 0; nq < 4; ++nq) {
                const int r = warp_n * 64 + nq * 16 + b_rowsel;
                const uint32_t bd = base + (uint32_t)(r * 128 +
                                     ((kb + b_koffb) ^ ((r & 7) << 4)));
                uint32_t t0, t1, t2, t3;
                ldsm4(t0, t1, t2, t3, bd + OFF_BH);
                bh[nq * 2][0] = t0; bh[nq * 2][1] = t1;
                bh[nq * 2 + 1][0] = t2; bh[nq * 2 + 1][1] = t3;
                ldsm4(t0, t1, t2, t3, bd + OFF_BL);
                bl[nq * 2][0] = t0; bl[nq * 2][1] = t1;
                bl[nq * 2 + 1][0] = t2; bl[nq * 2 + 1][1] = t3;
            }

#pragma unroll
            for (int mb = 0; mb < 2; ++mb)
#pragma unroll
                for (int nb = 0; nb < 8; ++nb) {
                    mma_bf16(c[mb][nb], ah[mb], bh[nb]);
                    mma_bf16(c[mb][nb], ah[mb], bl[nb]);
                    mma_bf16(c[mb][nb], al[mb], bh[nb]);
                }
        }
        __syncthreads();
    }

    const int gr = lane >> 2;
    const int gc = (lane & 3) * 2;
#pragma unroll
    for (int mb = 0; mb < 2; ++mb) {
        const int row0 = bm + warp_m * 32 + mb * 16 + gr;
#pragma unroll
        for (int nb = 0; nb < 8; ++nb) {
            const int col = bn + warp_n * 64 + nb * 8 + gc;
            *(float2*)(C + (size_t)row0 * CV + col) =
                make_float2(c[mb][nb][0], c[mb][nb][1]);
            *(float2*)(C + (size_t)(row0 + 8) * CV + col) =
                make_float2(c[mb][nb][2], c[mb][nb][3]);
        }
    }
}

// ---------------------------------------------------------------------------
// RoPE on q and k + bf16 hi/lo conversion. Thread per (b,t,h,j<32).
// ---------------------------------------------------------------------------
__global__ void rope_conv()
{
    const int idx = blockIdx.x * blockDim.x + threadIdx.x;
    const int j = idx & 31;
    const int h = (idx >> 5) & (HV - 1);
    const int t = (idx >> 9) & (TV - 1);
    const int b = idx >> 20;

    const float L2_10000 = 13.287712379549449f;
    const float invf = exp2f(-(float)j * (L2_10000 / 32.0f));
    const float ang = (float)t * invf;
    float sn, cs;
    sincosf(ang, &sn, &cs);

    const size_t base = (size_t)(b * TV + t) * CV + h * DHV + j;

    float q1 = g_q[base], q2 = g_q[base + 32];
    float qa = q1 * cs - q2 * sn;
    float qb = q2 * cs + q1 * sn;
    float k1 = g_k[base], k2 = g_k[base + 32];
    float ka = k1 * cs - k2 * sn;
    float kb = k2 * cs + k1 * sn;

    __nv_bfloat16 hqa = __float2bfloat16(qa);
    __nv_bfloat16 hqb = __float2bfloat16(qb);
    __nv_bfloat16 hka = __float2bfloat16(ka);
    __nv_bfloat16 hkb = __float2bfloat16(kb);
    g_qh[base]      = hqa;
    g_qh[base + 32] = hqb;
    g_ql[base]      = __float2bfloat16(qa - __bfloat162float(hqa));
    g_ql[base + 32] = __float2bfloat16(qb - __bfloat162float(hqb));
    g_kh[base]      = hka;
    g_kh[base + 32] = hkb;
    g_kl[base]      = __float2bfloat16(ka - __bfloat162float(hka));
    g_kl[base + 32] = __float2bfloat16(kb - __bfloat162float(hkb));
}

// ---------------------------------------------------------------------------
// v transpose + hi/lo: g_v [b*T+t][h*64+d] -> g_vth/g_vtl [bh][d][t].
// Block: (ttile, bh), 256 threads, 64x64 tile via smem.
// ---------------------------------------------------------------------------
__global__ __launch_bounds__(256)
void vtrans()
{
    __shared__ float vt[64][65];
    const int bh = blockIdx.y;
    const int b = bh >> 4, h = bh & 15;
    const int t0 = blockIdx.x * 64;
    const int tid = threadIdx.x;

#pragma unroll
    for (int it = 0; it < 4; ++it) {
        const int idx = it * 256 + tid;      // 1024 float4 slots
        const int row = idx >> 4;            // t within tile
        const int c4 = (idx & 15) * 4;       // d
        float4 v = *(const float4*)(g_v + (size_t)(b * TV + t0 + row) * CV + h * DHV + c4);
        vt[row][c4 + 0] = v.x; vt[row][c4 + 1] = v.y;
        vt[row][c4 + 2] = v.z; vt[row][c4 + 3] = v.w;
    }
    __syncthreads();

#pragma unroll
    for (int it = 0; it < 4; ++it) {
        const int idx = it * 256 + tid;
        const int d = idx >> 4;              // output row
        const int tc = (idx & 15) * 4;       // t chunk
        float x0 = vt[tc + 0][d], x1 = vt[tc + 1][d];
        float x2 = vt[tc + 2][d], x3 = vt[tc + 3][d];
        uint32_t h01 = pack_bf16(x0, x1);
        uint32_t h23 = pack_bf16(x2, x3);
        float r0 = x0 - bf16lo_f32(h01), r1 = x1 - bf16hi_f32(h01);
        float r2 = x2 - bf16lo_f32(h23), r3 = x3 - bf16hi_f32(h23);
        uint32_t l01 = pack_bf16(r0, r1);
        uint32_t l23 = pack_bf16(r2, r3);
        const size_t off = (size_t)(bh * DHV + d) * TV + t0 + tc;
        *(uint2*)(g_vth + off) = make_uint2(h01, h23);
        *(uint2*)(g_vtl + off) = make_uint2(l01, l23);
    }
}

// ---------------------------------------------------------------------------
// Retention attention on tensor cores (bf16 hi/lo, mma.sync m16n8k16) with
// fused GroupNorm epilogue writing bf16 hi/lo into the out-proj input.
// Block: (qt of 64 rows, bh). 4 warps; warp w owns q rows [16w, 16w+16).
// SMEM: qh/ql 8K each, kh/kl 8K, vth/vtl 8K = 48KB. Rows are 128B, XOR swizzle.
// ---------------------------------------------------------------------------
#define AQH 0
#define AQL 8192
#define AKH 16384
#define AKL 24576
#define AVH 32768
#define AVL 40960
#define ATTN_SMEM 49152

__global__ __launch_bounds__(128)
void retention_mma(const float* __restrict__ gn_w, const float* __restrict__ gn_b)
{
    extern __shared__ char smem[];
    const uint32_t sb = smem_to_u32(smem);
    const int tid = threadIdx.x;
    const int w = tid >> 5;
    const int lane = tid & 31;

    const int qt = (int)(gridDim.x - 1 - blockIdx.x);   // big tiles first
    const int bh = blockIdx.y;
    const int b = bh >> 4, h = bh & 15;
    const int tq0 = qt * 64;

    const int g = lane >> 2;        // accumulator row group
    const int t4 = lane & 3;        // accumulator col group

    const float gamma = 1.0f - __int_as_float((127 - 5 - h) << 23);
    const float l2g = log2f(gamma);
    const float ginv1 = fast_exp2(-l2g);
    const float ginv8 = fast_exp2(-8.0f * l2g);
    const float gpow8 = fast_exp2(8.0f * l2g);
    const float ctf = fast_exp2(-2.0f * (float)t4 * l2g);

    // ---- load q tile, build persistent A fragments ----
#pragma unroll
    for (int it = 0; it < 4; ++it) {
        const int idx = it * 128 + tid;
        const int row = idx >> 3;
        const int colb = (idx & 7) * 16;
        const uint32_t sw = (uint32_t)(row * 128 + (colb ^ ((row & 7) << 4)));
        const size_t gq = (size_t)(b * TV + tq0 + row) * CV + h * DHV + (colb >> 1);
        cp16(sb + AQH + sw, g_qh + gq);
        cp16(sb + AQL + sw, g_ql + gq);
    }
    cp_commit(); cp_wait0();
    __syncthreads();

    uint32_t qfh[4][4], qfl[4][4];
    {
        const int ar = w * 16 + (lane & 15);
        const int ak = ((lane >> 4) & 1) * 16;
#pragma unroll
        for (int ks = 0; ks < 4; ++ks) {
            const uint32_t ad = sb + (uint32_t)(ar * 128 + ((ks * 32 + ak) ^ ((ar & 7) << 4)));
            ldsm4(qfh[ks][0], qfh[ks][1], qfh[ks][2], qfh[ks][3], ad + AQH);
            ldsm4(qfl[ks][0], qfl[ks][1], qfl[ks][2], qfl[ks][3], ad + AQL);
        }
    }

    float o[8][4];
#pragma unroll
    for (int nb = 0; nb < 8; ++nb)
#pragma unroll
        for (int e = 0; e < 4; ++e) o[nb][e] = 0.f;

    const int b_row = (lane & 7) + ((lane >> 4) & 1) * 8;
    const int b_koffb = ((lane >> 3) & 1) * 16;

    for (int kt = 0; kt <= qt; ++kt) {
        const int tk0 = kt * 64;

        // load k (hi/lo) and v^T (hi/lo) tiles
#pragma unroll
        for (int it = 0; it < 4; ++it) {
            const int idx = it * 128 + tid;
            const int row = idx >> 3;
            const int colb = (idx & 7) * 16;
            const uint32_t sw = (uint32_t)(row * 128 + (colb ^ ((row & 7) << 4)));
            const size_t gk = (size_t)(b * TV + tk0 + row) * CV + h * DHV + (colb >> 1);
            const size_t gv = (size_t)(bh * DHV + row) * TV + tk0 + (colb >> 1);
            cp16(sb + AKH + sw, g_kh + gk);
            cp16(sb + AKL + sw, g_kl + gk);
            cp16(sb + AVH + sw, g_vth + gv);
            cp16(sb + AVL + sw, g_vtl + gv);
        }
        cp_commit(); cp_wait0();
        __syncthreads();

        // ---- S = q k^T (3-term hi/lo) ----
        float s[8][4];
#pragma unroll
        for (int nb = 0; nb < 8; ++nb)
#pragma unroll
            for (int e = 0; e < 4; ++e) s[nb][e] = 0.f;

#pragma unroll
        for (int ks = 0; ks < 4; ++ks) {
#pragma unroll
            for (int nq = 0; nq < 4; ++nq) {
                const int r = nq * 16 + b_row;
                const uint32_t bd = sb + (uint32_t)(r * 128 +
                                     ((ks * 32 + b_koffb) ^ ((r & 7) << 4)));
                uint32_t h0, h1, h2, h3, l0, l1, l2, l3;
                ldsm4(h0, h1, h2, h3, bd + AKH);
                ldsm4(l0, l1, l2, l3, bd + AKL);
                uint32_t bh0[2] = {h0, h1}, bh1[2] = {h2, h3};
                uint32_t bl0[2] = {l0, l1}, bl1[2] = {l2, l3};
                mma_bf16(s[nq * 2],     qfh[ks], bh0);
                mma_bf16(s[nq * 2],     qfh[ks], bl0);
                mma_bf16(s[nq * 2],     qfl[ks], bh0);
                mma_bf16(s[nq * 2 + 1], qfh[ks], bh1);
                mma_bf16(s[nq * 2 + 1], qfh[ks], bl1);
                mma_bf16(s[nq * 2 + 1], qfl[ks], bh1);
            }
        }

        // ---- decay * scale (factored; 1 MUFU per ktile) ----
        const int dbase = tq0 - tk0;
        const float rf0 = 0.125f * fast_exp2((float)(dbase + w * 16 + g) * l2g);
        const float rf8 = rf0 * gpow8;
        float cf = ctf;
        if (kt < qt) {
#pragma unroll
            for (int nb = 0; nb < 8; ++nb) {
                const float c0f = cf, c1f = cf * ginv1;
                s[nb][0] *= rf0 * c0f;
                s[nb][1] *= rf0 * c1f;
                s[nb][2] *= rf8 * c0f;
                s[nb][3] *= rf8 * c1f;
                cf *= ginv8;
            }
        } else {
            const int r0 = w * 16 + g, r1 = r0 + 8;
#pragma unroll
            for (int nb = 0; nb < 8; ++nb) {
                const int j0 = 8 * nb + 2 * t4;
                const float c0f = cf, c1f = cf * ginv1;
                s[nb][0] = (r0 >= j0)     ? s[nb][0] * rf0 * c0f : 0.f;
                s[nb][1] = (r0 >= j0 + 1) ? s[nb][1] * rf0 * c1f : 0.f;
                s[nb][2] = (r1 >= j0)     ? s[nb][2] * rf8 * c0f : 0.f;
                s[nb][3] = (r1 >= j0 + 1) ? s[nb][3] * rf8 * c1f : 0.f;
                cf *= ginv8;
            }
        }

        // ---- S -> bf16 hi/lo A-fragments (C layout == A layout) ----
        uint32_t sah[4][4], sal[4][4];
#pragma unroll
        for (int kc = 0; kc < 4; ++kc) {
            const int n0 = 2 * kc, n1 = 2 * kc + 1;
            uint32_t p;
            p = pack_bf16(s[n0][0], s[n0][1]);
            sah[kc][0] = p;
            sal[kc][0] = pack_bf16(s[n0][0] - bf16lo_f32(p), s[n0][1] - bf16hi_f32(p));
            p = pack_bf16(s[n0][2], s[n0][3]);
            sah[kc][1] = p;
            sal[kc][1] = pack_bf16(s[n0][2] - bf16lo_f32(p), s[n0][3] - bf16hi_f32(p));
            p = pack_bf16(s[n1][0], s[n1][1]);
            sah[kc][2] = p;
            sal[kc][2] = pack_bf16(s[n1][0] - bf16lo_f32(p), s[n1][1] - bf16hi_f32(p));
            p = pack_bf16(s[n1][2], s[n1][3]);
            sah[kc][3] = p;
            sal[kc][3] = pack_bf16(s[n1][2] - bf16lo_f32(p), s[n1][3] - bf16hi_f32(p));
        }

        // ---- O += S v (3-term hi/lo) ----
#pragma unroll
        for (int kc = 0; kc < 4; ++kc) {
#pragma unroll
            for (int nq = 0; nq < 4; ++nq) {
                const int r = nq * 16 + b_row;
                const uint32_t bd = sb + (uint32_t)(r * 128 +
                                     ((kc * 32 + b_koffb) ^ ((r & 7) << 4)));
                uint32_t h0, h1, h2, h3, l0, l1, l2, l3;
                ldsm4(h0, h1, h2, h3, bd + AVH);
                ldsm4(l0, l1, l2, l3, bd + AVL);
                uint32_t vh0[2] = {h0, h1}, vh1[2] = {h2, h3};
                uint32_t vl0[2] = {l0, l1}, vl1[2] = {l2, l3};
                mma_bf16(o[nq * 2],     sah[kc], vh0);
                mma_bf16(o[nq * 2],     sah[kc], vl0);
                mma_bf16(o[nq * 2],     sal[kc], vh0);
                mma_bf16(o[nq * 2 + 1], sah[kc], vh1);
                mma_bf16(o[nq * 2 + 1], sah[kc], vl1);
                mma_bf16(o[nq * 2 + 1], sal[kc], vh1);
            }
        }
        __syncthreads();   // protect k/v smem before next ktile load
    }

    // ---- fused GroupNorm + bf16 hi/lo store into out-proj input ----
    float sum0 = 0.f, sq0 = 0.f, sum1 = 0.f, sq1 = 0.f;
#pragma unroll
    for (int nb = 0; nb < 8; ++nb) {
        sum0 += o[nb][0] + o[nb][1];
        sq0  += o[nb][0] * o[nb][0] + o[nb][1] * o[nb][1];
        sum1 += o[nb][2] + o[nb][3];
        sq1  += o[nb][2] * o[nb][2] + o[nb][3] * o[nb][3];
    }
#pragma unroll
    for (int off = 1; off < 4; off <<= 1) {
        sum0 += __shfl_xor_sync(0xffffffffu, sum0, off);
        sq0  += __shfl_xor_sync(0xffffffffu, sq0,  off);
        sum1 += __shfl_xor_sync(0xffffffffu, sum1, off);
        sq1  += __shfl_xor_sync(0xffffffffu, sq1,  off);
    }
    const float invn = 1.0f / 64.0f;
    const float mean0 = sum0 * invn;
    const float mean1 = sum1 * invn;
    const float rs0 = rsqrtf(sq0 * invn - mean0 * mean0 + 1e-5f);
    const float rs1 = rsqrtf(sq1 * invn - mean1 * mean1 + 1e-5f);

    const int row0 = tq0 + w * 16 + g;
    const size_t base0 = (size_t)(b * TV + row0) * CV + h * DHV;
    const size_t base1 = base0 + (size_t)8 * CV;

#pragma unroll
    for (int nb = 0; nb < 8; ++nb) {
        const int d0 = 8 * nb + 2 * t4;
        const float2 wv = *(const float2*)(gn_w + h * DHV + d0);
        const float2 bv = *(const float2*)(gn_b + h * DHV + d0);
        float y00 = (o[nb][0] - mean0) * rs0 * wv.x + bv.x;
        float y01 = (o[nb][1] - mean0) * rs0 * wv.y + bv.y;
        float y10 = (o[nb][2] - mean1) * rs1 * wv.x + bv.x;
        float y11 = (o[nb][3] - mean1) * rs1 * wv.y + bv.y;

        uint32_t p0 = pack_bf16(y00, y01);
        uint32_t q0 = pack_bf16(y00 - bf16lo_f32(p0), y01 - bf16hi_f32(p0));
        uint32_t p1 = pack_bf16(y10, y11);
        uint32_t q1 = pack_bf16(y10 - bf16lo_f32(p1), y11 - bf16hi_f32(p1));

        *(uint32_t*)(g_xh + base0 + d0) = p0;
        *(uint32_t*)(g_xl + base0 + d0) = q0;
        *(uint32_t*)(g_xh + base1 + d0) = p1;
        *(uint32_t*)(g_xl + base1 + d0) = q1;
    }
}

// ---------------------------------------------------------------------------
extern "C" void kernel_launch(void* const* d_in, const int* in_sizes, int n_in,
                              void* d_out, int out_size)
{
    const float* x   = (const float*)d_in[0];
    const float* Wq  = (const float*)d_in[1];
    const float* Wk  = (const float*)d_in[2];
    const float* Wv  = (const float*)d_in[3];
    const float* Wo  = (const float*)d_in[4];
    const float* gnw = (const float*)d_in[5];
    const float* gnb = (const float*)d_in[6];
    float* out = (float*)d_out;

    float *q, *k, *v;
    __nv_bfloat16 *xh, *xl, *wh, *wl, *woh, *wol;
    cudaGetSymbolAddress((void**)&q, g_q);
    cudaGetSymbolAddress((void**)&k, g_k);
    cudaGetSymbolAddress((void**)&v, g_v);
    cudaGetSymbolAddress((void**)&xh, g_xh);
    cudaGetSymbolAddress((void**)&xl, g_xl);
    cudaGetSymbolAddress((void**)&wh, g_wh);
    cudaGetSymbolAddress((void**)&wl, g_wl);
    cudaGetSymbolAddress((void**)&woh, g_woh);
    cudaGetSymbolAddress((void**)&wol, g_wol);

    cudaFuncSetAttribute(bfgemm,
                         cudaFuncAttributeMaxDynamicSharedMemorySize, GEMM_SMEM);
    cudaFuncSetAttribute(retention_mma,
                         cudaFuncAttributeMaxDynamicSharedMemorySize, ATTN_SMEM);

    const int WN4 = CV * CV / 4;
    const int XN4 = MV * CV / 4;

    // 0) hi/lo bf16 splits of inputs
    conv_hilo<<<XN4 / 256, 256>>>(x, xh, xl, XN4);
    conv_hilo<<<WN4 / 256, 256>>>(Wq, wh,                       wl,                       WN4);
    conv_hilo<<<WN4 / 256, 256>>>(Wk, wh + (size_t)CV * CV,     wl + (size_t)CV * CV,     WN4);
    conv_hilo<<<WN4 / 256, 256>>>(Wv, wh + (size_t)2 * CV * CV, wl + (size_t)2 * CV * CV, WN4);
    conv_hilo<<<WN4 / 256, 256>>>(Wo, woh, wol, WN4);

    // 1) QKV projections (tensor cores)
    bfgemm<<<dim3(CV / 128, MV / 128, 3), 256, GEMM_SMEM>>>(xh, xl, wh, wl, q, k, v);
    // 2) RoPE + bf16 hi/lo q,k
    rope_conv<<<(BV * TV * HV * 32) / 256, 256>>>();
    // 3) v transpose + hi/lo
    vtrans<<<dim3(TV / 64, BV * HV), 256>>>();
    // 4) Retention on tensor cores + fused GroupNorm -> g_xh/g_xl
    retention_mma<<<dim3(TV / 64, BV * HV), 128, ATTN_SMEM>>>(gnw, gnb);
    // 5) Output projection (tensor cores)
    bfgemm<<<dim3(CV / 128, MV / 128, 1), 256, GEMM_SMEM>>>(xh, xl, woh, wol, out, out, out);
}